// round 5
// baseline (speedup 1.0000x reference)
#include <cuda_runtime.h>
#include <cstdint>
#include <cstddef>

// ---------------------------------------------------------------------------
// InjectedSODA_SVD: out = x @ ( (Q1⊗Q2⊗Q3) @ ((U*relu(S+delta)) @ V)^T )
// x: [4,4096,3072] f32, U:[3072,3072], S:[3072], V:[3072,3072], delta:[3072],
// Q1:[16,16], Q2:[16,16], Q3:[12,12].  out: [4,4096,3072] f32.
//
// Pipeline (all fp32, packed f32x2 FMA in the GEMMs):
//   1) Ut[k,o] = U[o,k] * relu(S[k]+delta[k])      (transpose+scale)
//   2) xT[d,m] = x[m,d]                            (transpose)
//   3) W0[d,o] = sum_k V[k,d] * Ut[k,o]            (TN GEMM, = W^T)
//   4) three Kronecker mode contractions (Q3, Q2, Q1) -> W_t[d,o]
//   5) out[m,o] = sum_d xT[d,m] * W_t[d,o]         (TN GEMM)
// ---------------------------------------------------------------------------

#define IN_F   3072
#define SEQ_M  16384            // 4*4096

// Scratch (device globals: allocations are forbidden)
__device__ __align__(16) float g_xT[(size_t)IN_F * SEQ_M];   // 201 MB
__device__ __align__(16) float g_Ut[(size_t)IN_F * IN_F];
__device__ __align__(16) float g_W0[(size_t)IN_F * IN_F];
__device__ __align__(16) float g_W1[(size_t)IN_F * IN_F];

// ---------------------------------------------------------------------------
// Transpose (+ optional row scaling by relu(S+delta)):
//   in:  [NJ][NI] row-major;  out: [NI][NJ];  out[i][j] = in[j][i] * s(i)
// ---------------------------------------------------------------------------
__global__ void transpose_scale_kernel(const float* __restrict__ in,
                                       float* __restrict__ out,
                                       int NJ, int NI,
                                       const float* __restrict__ S,
                                       const float* __restrict__ D)
{
    __shared__ float t[32][33];
    const int i0 = blockIdx.y * 32;
    const int j0 = blockIdx.x * 32;
    const int x = threadIdx.x, y = threadIdx.y;
#pragma unroll
    for (int r = 0; r < 4; r++)
        t[y + 8 * r][x] = in[(size_t)(j0 + y + 8 * r) * NI + (i0 + x)];
    __syncthreads();
#pragma unroll
    for (int r = 0; r < 4; r++) {
        const int i = i0 + y + 8 * r;
        float s = 1.0f;
        if (S) s = fmaxf(S[i] + D[i], 0.0f);
        out[(size_t)i * NJ + (j0 + x)] = t[x][y + 8 * r] * s;
    }
}

// ---------------------------------------------------------------------------
// Kronecker mode contraction:
//   rows decompose as row = a*(R*I) + j*I + c, a in [0,O), c in [0,I)
//   out[a*(R*I) + i*I + c][o] = sum_j Q[i*R+j] * in[a*(R*I) + j*I + c][o]
// grid: (3072/256, O*I), block 256 (one o per thread).
// ---------------------------------------------------------------------------
__global__ void kron_stage_kernel(const float* __restrict__ in,
                                  float* __restrict__ out,
                                  const float* __restrict__ Q,
                                  int R, int I)
{
    __shared__ float sQ[256];
    __shared__ float sIn[16][256];
    const int tid = threadIdx.x;
    const int o = blockIdx.x * 256 + tid;
    const int a = blockIdx.y / I;
    const int c = blockIdx.y % I;
    if (tid < R * R) sQ[tid] = Q[tid];
    const int rbase = a * R * I + c;
    for (int j = 0; j < R; j++)
        sIn[j][tid] = in[(size_t)(rbase + j * I) * IN_F + o];
    __syncthreads();
    for (int i = 0; i < R; i++) {
        float acc = 0.0f;
        for (int j = 0; j < R; j++)
            acc = fmaf(sQ[i * R + j], sIn[j][tid], acc);
        out[(size_t)(rbase + i * I) * IN_F + o] = acc;
    }
}

// ---------------------------------------------------------------------------
// TN GEMM with packed f32x2 FMA:  C[m][n] = sum_k A[k*M+m] * B[k*N+n]
// Block tile 128x128x16, 256 threads, 8x8 per thread.
// A is stored DUPLICATED in smem (each value twice) so the broadcast operand
// of fma.rn.f32x2 is a direct 8-byte LDS (no register packing MOVs).
// All dims must be multiples of the tile sizes (true for this problem).
// ---------------------------------------------------------------------------
#define BM 128
#define BN 128
#define BK 16

#if __CUDA_ARCH__ >= 1000
#define FFMA2(d, a, b) asm("fma.rn.f32x2 %0, %1, %2, %0;" : "+l"(d) : "l"(a), "l"(b))
#else
// fallback: scalar (not expected to be used on sm_103a)
__device__ __forceinline__ void ffma2_fallback(unsigned long long& d,
                                               unsigned long long a,
                                               unsigned long long b) {
    float2 dd = *(float2*)&d, aa = *(float2*)&a, bb = *(float2*)&b;
    dd.x = fmaf(aa.x, bb.x, dd.x);
    dd.y = fmaf(aa.y, bb.y, dd.y);
    d = *(unsigned long long*)&dd;
}
#define FFMA2(d, a, b) ffma2_fallback(d, a, b)
#endif

__global__ __launch_bounds__(256, 1)
void gemm_tn_f32x2(const float* __restrict__ A, const float* __restrict__ B,
                   float* __restrict__ C, int M, int N, int K)
{
    __shared__ __align__(16) float As2[2][BK][2 * BM];  // duplicated A: 32 KB
    __shared__ __align__(16) float Bs[2][BK][BN];       // 16 KB

    const int tid = threadIdx.x;
    const int bm = blockIdx.y * BM;
    const int bn = blockIdx.x * BN;
    const int tx = tid & 15;          // n-group (0..15)
    const int ty = tid >> 4;          // m-group (0..15)
    const int row_m = ty * 8;
    const int col_n = tx * 8;

    // global tile load mapping: 512 float4 per operand tile, 2 per thread
    const int lk  = tid >> 5;         // k-row 0..7 (and +8)
    const int lc4 = (tid & 31) << 2;  // col 0..124 step 4

    const float* Ag = A + bm + lc4;
    const float* Bg = B + bn + lc4;

    unsigned long long acc[8][4];
#pragma unroll
    for (int i = 0; i < 8; i++)
#pragma unroll
        for (int j = 0; j < 4; j++) acc[i][j] = 0ull;

    float4 ra0, ra1, rb0, rb1;

    // prologue: tile 0 -> buffer 0
    ra0 = *(const float4*)(Ag + (size_t)lk * M);
    ra1 = *(const float4*)(Ag + (size_t)(lk + 8) * M);
    rb0 = *(const float4*)(Bg + (size_t)lk * N);
    rb1 = *(const float4*)(Bg + (size_t)(lk + 8) * N);
    {
        const float* a0 = (const float*)&ra0;
        const float* a1 = (const float*)&ra1;
#pragma unroll
        for (int e = 0; e < 4; e++) {
            *(float2*)&As2[0][lk][(lc4 + e) * 2]     = make_float2(a0[e], a0[e]);
            *(float2*)&As2[0][lk + 8][(lc4 + e) * 2] = make_float2(a1[e], a1[e]);
        }
        *(float4*)&Bs[0][lk][lc4]     = rb0;
        *(float4*)&Bs[0][lk + 8][lc4] = rb1;
    }
    __syncthreads();

    const int KT = K / BK;
    for (int kt = 0; kt < KT; kt++) {
        const int cur = kt & 1;
        const int nxt = cur ^ 1;
        const bool has_next = (kt + 1 < KT);

        if (has_next) {
            const float* Ak = Ag + (size_t)(kt + 1) * BK * M;
            const float* Bk = Bg + (size_t)(kt + 1) * BK * N;
            ra0 = *(const float4*)(Ak + (size_t)lk * M);
            ra1 = *(const float4*)(Ak + (size_t)(lk + 8) * M);
            rb0 = *(const float4*)(Bk + (size_t)lk * N);
            rb1 = *(const float4*)(Bk + (size_t)(lk + 8) * N);
        }

#pragma unroll
        for (int kk = 0; kk < BK; kk++) {
            const ulonglong2* ap = (const ulonglong2*)&As2[cur][kk][row_m * 2];
            const ulonglong2* bp = (const ulonglong2*)&Bs[cur][kk][col_n];
            ulonglong2 a01 = ap[0], a23 = ap[1], a45 = ap[2], a67 = ap[3];
            ulonglong2 b03 = bp[0], b47 = bp[1];
            unsigned long long av[8] = {a01.x, a01.y, a23.x, a23.y,
                                        a45.x, a45.y, a67.x, a67.y};
            unsigned long long bv[4] = {b03.x, b03.y, b47.x, b47.y};
#pragma unroll
            for (int i = 0; i < 8; i++)
#pragma unroll
                for (int j = 0; j < 4; j++)
                    FFMA2(acc[i][j], av[i], bv[j]);
        }

        if (has_next) {
            const float* a0 = (const float*)&ra0;
            const float* a1 = (const float*)&ra1;
#pragma unroll
            for (int e = 0; e < 4; e++) {
                *(float2*)&As2[nxt][lk][(lc4 + e) * 2]     = make_float2(a0[e], a0[e]);
                *(float2*)&As2[nxt][lk + 8][(lc4 + e) * 2] = make_float2(a1[e], a1[e]);
            }
            *(float4*)&Bs[nxt][lk][lc4]     = rb0;
            *(float4*)&Bs[nxt][lk + 8][lc4] = rb1;
        }
        __syncthreads();
    }

    // epilogue: 8 rows x 8 cols per thread, 16B vector stores
#pragma unroll
    for (int i = 0; i < 8; i++) {
        float* crow = C + (size_t)(bm + row_m + i) * N + bn + col_n;
        ulonglong2 v0; v0.x = acc[i][0]; v0.y = acc[i][1];
        ulonglong2 v1; v1.x = acc[i][2]; v1.y = acc[i][3];
        *(ulonglong2*)(crow)     = v0;
        *(ulonglong2*)(crow + 4) = v1;
    }
}

// ---------------------------------------------------------------------------
// Launch
// ---------------------------------------------------------------------------
extern "C" void kernel_launch(void* const* d_in, const int* in_sizes, int n_in,
                              void* d_out, int out_size)
{
    const float* x   = (const float*)d_in[0];
    const float* U   = (const float*)d_in[1];
    const float* S   = (const float*)d_in[2];
    const float* V   = (const float*)d_in[3];
    const float* dlt = (const float*)d_in[4];
    const float* Q1  = (const float*)d_in[5];
    const float* Q2  = (const float*)d_in[6];
    const float* Q3  = (const float*)d_in[7];
    float* out = (float*)d_out;

    float *xT, *Ut, *W0, *W1;
    cudaGetSymbolAddress((void**)&xT, g_xT);
    cudaGetSymbolAddress((void**)&Ut, g_Ut);
    cudaGetSymbolAddress((void**)&W0, g_W0);
    cudaGetSymbolAddress((void**)&W1, g_W1);

    // 1) Ut[k,o] = U[o,k] * relu(S[k]+delta[k])
    transpose_scale_kernel<<<dim3(IN_F / 32, IN_F / 32), dim3(32, 8)>>>(
        U, Ut, IN_F, IN_F, S, dlt);

    // 2) xT[d,m] = x[m,d]
    transpose_scale_kernel<<<dim3(SEQ_M / 32, IN_F / 32), dim3(32, 8)>>>(
        x, xT, SEQ_M, IN_F, nullptr, nullptr);

    // 3) W0[d,o] = sum_k V[k,d] * Ut[k,o]   (= W^T)
    gemm_tn_f32x2<<<dim3(IN_F / BN, IN_F / BM), 256>>>(
        V, Ut, W0, IN_F, IN_F, IN_F);

    // 4) Kronecker: contract j3 (Q3), then j2 (Q2), then j1 (Q1)
    //    d = (j1*16 + j2)*12 + j3
    kron_stage_kernel<<<dim3(IN_F / 256, 256), 256>>>(W0, W1, Q3, 12, 1);
    kron_stage_kernel<<<dim3(IN_F / 256, 192), 256>>>(W1, W0, Q2, 16, 12);
    kron_stage_kernel<<<dim3(IN_F / 256, 192), 256>>>(W0, W1, Q1, 16, 192);

    // 5) out[m,o] = sum_d xT[d,m] * W_t[d,o]
    gemm_tn_f32x2<<<dim3(IN_F / BN, SEQ_M / BM), 256>>>(
        xT, W1, out, SEQ_M, IN_F, IN_F);
}

// round 7
// speedup vs baseline: 4.1284x; 4.1284x over previous
#include <cuda_runtime.h>
#include <cuda_bf16.h>
#include <cstdint>
#include <cstddef>

// ---------------------------------------------------------------------------
// InjectedSODA_SVD: out = x @ ( (Q1⊗Q2⊗Q3) @ ((U*relu(S+delta)) @ V)^T )
//
// bf16 hi/lo split + warp-level mma.sync (m16n8k16, bf16 -> f32):
//   A @ B ≈ Ahi@Bhi + Ahi@Blo + Alo@Bhi  (fp32 accumulation)
// (tcgen05 is unavailable: harness compiles via a compute_103 family PTX
//  target; only base-target PTX — mma.sync/ldmatrix/cp.async — is legal.)
//
// Pipeline:
//   1) split x -> x_hi/x_lo  [M,K] K-major        (elementwise)
//   2) V -> VT_hi/lo [d,k]                        (transpose+split)
//   3) U*relu(S+delta) -> Us_hi/lo [o,k]          (scale+split)
//   4) W^T[d,o] = VT @ Us^T                       (warp-MMA GEMM, fp32 out)
//   5) kron stages Q3,Q2,Q1 (fp32)
//   6) W_t[d,o] -> Wt_hi/lo [o,d]                 (transpose+split)
//   7) out[m,o] = x @ Wt^T                        (warp-MMA GEMM)
// ---------------------------------------------------------------------------

#define IN_F   3072
#define SEQ_M  16384

// ---------------- scratch (device globals; allocation is forbidden) --------
__device__ __align__(1024) __nv_bfloat16 g_xhi[(size_t)SEQ_M * IN_F];
__device__ __align__(1024) __nv_bfloat16 g_xlo[(size_t)SEQ_M * IN_F];
__device__ __align__(1024) __nv_bfloat16 g_VThi[(size_t)IN_F * IN_F];
__device__ __align__(1024) __nv_bfloat16 g_VTlo[(size_t)IN_F * IN_F];
__device__ __align__(1024) __nv_bfloat16 g_Ushi[(size_t)IN_F * IN_F];
__device__ __align__(1024) __nv_bfloat16 g_Uslo[(size_t)IN_F * IN_F];
__device__ __align__(1024) __nv_bfloat16 g_Wthi[(size_t)IN_F * IN_F];
__device__ __align__(1024) __nv_bfloat16 g_Wtlo[(size_t)IN_F * IN_F];
__device__ __align__(1024) float g_W0[(size_t)IN_F * IN_F];
__device__ __align__(1024) float g_W1[(size_t)IN_F * IN_F];

// ---------------- PTX helpers (base-target only) ----------------------------
__device__ __forceinline__ uint32_t smem_u32(const void* p) {
    uint32_t a;
    asm("{ .reg .u64 t; cvta.to.shared.u64 t, %1; cvt.u32.u64 %0, t; }"
        : "=r"(a) : "l"(p));
    return a;
}
__device__ __forceinline__ uint32_t swz128(uint32_t o) {
    return o ^ ((o >> 3) & 0x70);
}
__device__ __forceinline__ void cp16(uint32_t dst, const void* src) {
    asm volatile("cp.async.cg.shared.global [%0], [%1], 16;"
                 :: "r"(dst), "l"(src));
}
__device__ __forceinline__ void ldsm4(uint32_t* r, uint32_t addr) {
    asm volatile("ldmatrix.sync.aligned.m8n8.x4.shared.b16 {%0,%1,%2,%3}, [%4];"
                 : "=r"(r[0]), "=r"(r[1]), "=r"(r[2]), "=r"(r[3])
                 : "r"(addr));
}
__device__ __forceinline__ void mma16816(float* c, const uint32_t* a,
                                         const uint32_t* b) {
    asm volatile(
        "mma.sync.aligned.m16n8k16.row.col.f32.bf16.bf16.f32 "
        "{%0,%1,%2,%3}, {%4,%5,%6,%7}, {%8,%9}, {%0,%1,%2,%3};"
        : "+f"(c[0]), "+f"(c[1]), "+f"(c[2]), "+f"(c[3])
        : "r"(a[0]), "r"(a[1]), "r"(a[2]), "r"(a[3]), "r"(b[0]), "r"(b[1]));
}

// ---------------- split helpers --------------------------------------------
__device__ __forceinline__ void split_bf16(float v, __nv_bfloat16& h,
                                           __nv_bfloat16& l) {
    h = __float2bfloat16(v);
    l = __float2bfloat16(v - __bfloat162float(h));
}

// ---------------------------------------------------------------------------
// split (+optional per-column scale relu(S[col]+D[col])): f32 -> hi/lo bf16
// ---------------------------------------------------------------------------
__global__ void split_scale_kernel(const float* __restrict__ in,
                                   const float* __restrict__ S,
                                   const float* __restrict__ D,
                                   __nv_bfloat16* __restrict__ hi,
                                   __nv_bfloat16* __restrict__ lo,
                                   size_t n4, int cols)
{
    size_t i = (size_t)blockIdx.x * blockDim.x + threadIdx.x;
    if (i >= n4) return;
    float4 v = ((const float4*)in)[i];
    if (S) {
        int c = (int)((i * 4) % (size_t)cols);
        v.x *= fmaxf(S[c + 0] + D[c + 0], 0.0f);
        v.y *= fmaxf(S[c + 1] + D[c + 1], 0.0f);
        v.z *= fmaxf(S[c + 2] + D[c + 2], 0.0f);
        v.w *= fmaxf(S[c + 3] + D[c + 3], 0.0f);
    }
    __nv_bfloat16 h[4], l[4];
    split_bf16(v.x, h[0], l[0]);
    split_bf16(v.y, h[1], l[1]);
    split_bf16(v.z, h[2], l[2]);
    split_bf16(v.w, h[3], l[3]);
    ((__nv_bfloat162*)hi)[i * 2 + 0] = __nv_bfloat162(h[0], h[1]);
    ((__nv_bfloat162*)hi)[i * 2 + 1] = __nv_bfloat162(h[2], h[3]);
    ((__nv_bfloat162*)lo)[i * 2 + 0] = __nv_bfloat162(l[0], l[1]);
    ((__nv_bfloat162*)lo)[i * 2 + 1] = __nv_bfloat162(l[2], l[3]);
}

// ---------------------------------------------------------------------------
// transpose + split: in [NJ][NI] f32 -> hi/lo [NI][NJ] bf16
// ---------------------------------------------------------------------------
__global__ void transpose_split_kernel(const float* __restrict__ in,
                                       __nv_bfloat16* __restrict__ hi,
                                       __nv_bfloat16* __restrict__ lo,
                                       int NJ, int NI)
{
    __shared__ float t[32][33];
    const int i0 = blockIdx.y * 32;
    const int j0 = blockIdx.x * 32;
    const int x = threadIdx.x, y = threadIdx.y;
#pragma unroll
    for (int r = 0; r < 4; r++)
        t[y + 8 * r][x] = in[(size_t)(j0 + y + 8 * r) * NI + (i0 + x)];
    __syncthreads();
#pragma unroll
    for (int r = 0; r < 4; r++) {
        const int i = i0 + y + 8 * r;
        __nv_bfloat16 h, l;
        split_bf16(t[x][y + 8 * r], h, l);
        hi[(size_t)i * NJ + (j0 + x)] = h;
        lo[(size_t)i * NJ + (j0 + x)] = l;
    }
}

// ---------------------------------------------------------------------------
// Kronecker mode contraction (fp32; unchanged from passing kernel)
// ---------------------------------------------------------------------------
__global__ void kron_stage_kernel(const float* __restrict__ in,
                                  float* __restrict__ out,
                                  const float* __restrict__ Q,
                                  int R, int I)
{
    __shared__ float sQ[256];
    __shared__ float sIn[16][256];
    const int tid = threadIdx.x;
    const int o = blockIdx.x * 256 + tid;
    const int a = blockIdx.y / I;
    const int c = blockIdx.y % I;
    if (tid < R * R) sQ[tid] = Q[tid];
    const int rbase = a * R * I + c;
    for (int j = 0; j < R; j++)
        sIn[j][tid] = in[(size_t)(rbase + j * I) * IN_F + o];
    __syncthreads();
    for (int i = 0; i < R; i++) {
        float acc = 0.0f;
        for (int j = 0; j < R; j++)
            acc = fmaf(sQ[i * R + j], sIn[j][tid], acc);
        out[(size_t)(rbase + i * I) * IN_F + o] = acc;
    }
}

// ---------------------------------------------------------------------------
// Warp-MMA split-bf16 GEMM: C[m][n] = sum_k (Ahi+Alo)[m][k]*(Bhi+Blo)[n][k]
// (lo*lo dropped). Block 128x128, K-chunk 64 bf16 (128B swizzled rows),
// 2-stage cp.async pipeline, 8 warps (2M x 4N), warp tile 64x32.
// M,N,K multiples of 128/128/64 (true here).
// ---------------------------------------------------------------------------
#define GKCH       64
#define TILE_OP_B  16384                  // 128 rows x 128 bytes
#define STAGE_B    (4 * TILE_OP_B)        // Ahi, Alo, Bhi, Blo
#define SOF_AH     0
#define SOF_AL     16384
#define SOF_BH     32768
#define SOF_BL     49152
#define GEMM_SMEM  (2 * STAGE_B + 1024)   // 132 KB

__device__ __forceinline__ void load_tiles(uint32_t sb,
                                           const char* pAh, const char* pAl,
                                           const char* pBh, const char* pBl,
                                           size_t ldb, size_t gbase, int tid)
{
#pragma unroll
    for (int i = 0; i < 4; i++) {
        int idx = tid + i * 256;
        int row = idx >> 3;
        uint32_t c16 = (uint32_t)(idx & 7) << 4;
        uint32_t so = swz128((uint32_t)row * 128u + c16);
        size_t go = (size_t)row * ldb + gbase + c16;
        cp16(sb + SOF_AH + so, pAh + go);
        cp16(sb + SOF_AL + so, pAl + go);
        cp16(sb + SOF_BH + so, pBh + go);
        cp16(sb + SOF_BL + so, pBl + go);
    }
}

__global__ __launch_bounds__(256, 1)
void mma_gemm_split(const __nv_bfloat16* __restrict__ Ahi,
                    const __nv_bfloat16* __restrict__ Alo,
                    const __nv_bfloat16* __restrict__ Bhi,
                    const __nv_bfloat16* __restrict__ Blo,
                    float* __restrict__ C, int M, int N, int K)
{
    extern __shared__ char dynsmem[];
    const int tid = threadIdx.x;
    const uint32_t smem = (smem_u32(dynsmem) + 1023u) & ~1023u;

    const int w = tid >> 5, lane = tid & 31;
    const int wm = w >> 2;                 // 0..1  (64-row slab)
    const int wn = w & 3;                  // 0..3  (32-col slab)
    const int m0 = wm * 64;
    const int n0 = wn * 32;

    // ldmatrix lane patterns
    const int rowA  = lane & 15;
    const uint32_t kselA = (uint32_t)(lane >> 4) << 4;       // 0 or 16
    const int rowB  = (lane & 7) + ((lane >> 4) << 3);
    const uint32_t kselB = (uint32_t)((lane >> 3) & 1) << 4; // 0 or 16

    const size_t ldb = (size_t)K * 2;
    const char* pAh = (const char*)Ahi + (size_t)blockIdx.y * 128 * ldb;
    const char* pAl = (const char*)Alo + (size_t)blockIdx.y * 128 * ldb;
    const char* pBh = (const char*)Bhi + (size_t)blockIdx.x * 128 * ldb;
    const char* pBl = (const char*)Blo + (size_t)blockIdx.x * 128 * ldb;

    float acc[4][4][4];
#pragma unroll
    for (int a = 0; a < 4; a++)
#pragma unroll
        for (int b = 0; b < 4; b++)
#pragma unroll
            for (int c = 0; c < 4; c++) acc[a][b][c] = 0.0f;

    const int KT = K / GKCH;

    // prologue: 2 stages
    load_tiles(smem, pAh, pAl, pBh, pBl, ldb, 0, tid);
    asm volatile("cp.async.commit_group;" ::: "memory");
    load_tiles(smem + STAGE_B, pAh, pAl, pBh, pBl, ldb, GKCH * 2, tid);
    asm volatile("cp.async.commit_group;" ::: "memory");

    for (int kc = 0; kc < KT; kc++) {
        const uint32_t sb = smem + (uint32_t)(kc & 1) * STAGE_B;

        asm volatile("cp.async.wait_group 1;" ::: "memory");
        __syncthreads();

#pragma unroll
        for (int kk = 0; kk < 4; kk++) {
            const uint32_t kb = (uint32_t)kk * 32;
            uint32_t ah[4][4], al[4][4], bh[2][4], bl[2][4];
#pragma unroll
            for (int mi = 0; mi < 4; mi++) {
                uint32_t off = swz128((uint32_t)(m0 + mi * 16 + rowA) * 128u
                                      + kb + kselA);
                ldsm4(ah[mi], sb + SOF_AH + off);
                ldsm4(al[mi], sb + SOF_AL + off);
            }
#pragma unroll
            for (int j = 0; j < 2; j++) {
                uint32_t off = swz128((uint32_t)(n0 + j * 16 + rowB) * 128u
                                      + kb + kselB);
                ldsm4(bh[j], sb + SOF_BH + off);
                ldsm4(bl[j], sb + SOF_BL + off);
            }
            // term 1: Ahi * Bhi
#pragma unroll
            for (int mi = 0; mi < 4; mi++)
#pragma unroll
                for (int ni = 0; ni < 4; ni++)
                    mma16816(acc[mi][ni], ah[mi], &bh[ni >> 1][(ni & 1) * 2]);
            // term 2: Ahi * Blo
#pragma unroll
            for (int mi = 0; mi < 4; mi++)
#pragma unroll
                for (int ni = 0; ni < 4; ni++)
                    mma16816(acc[mi][ni], ah[mi], &bl[ni >> 1][(ni & 1) * 2]);
            // term 3: Alo * Bhi
#pragma unroll
            for (int mi = 0; mi < 4; mi++)
#pragma unroll
                for (int ni = 0; ni < 4; ni++)
                    mma16816(acc[mi][ni], al[mi], &bh[ni >> 1][(ni & 1) * 2]);
        }

        __syncthreads();
        if (kc + 2 < KT)
            load_tiles(sb, pAh, pAl, pBh, pBl, ldb,
                       (size_t)(kc + 2) * (GKCH * 2), tid);
        asm volatile("cp.async.commit_group;" ::: "memory");
    }

    // epilogue: direct f32 stores (float2 per mma row-half)
    const int g = lane >> 2, t2 = (lane & 3) * 2;
    const size_t rbase = (size_t)blockIdx.y * 128 + m0;
    const size_t cbase = (size_t)blockIdx.x * 128 + n0;
#pragma unroll
    for (int mi = 0; mi < 4; mi++) {
#pragma unroll
        for (int ni = 0; ni < 4; ni++) {
            float* p0 = C + (rbase + mi * 16 + g) * (size_t)N
                          + cbase + ni * 8 + t2;
            float* p1 = p0 + 8 * (size_t)N;
            *(float2*)p0 = make_float2(acc[mi][ni][0], acc[mi][ni][1]);
            *(float2*)p1 = make_float2(acc[mi][ni][2], acc[mi][ni][3]);
        }
    }
}

// ---------------------------------------------------------------------------
// Launch
// ---------------------------------------------------------------------------
extern "C" void kernel_launch(void* const* d_in, const int* in_sizes, int n_in,
                              void* d_out, int out_size)
{
    (void)in_sizes; (void)n_in; (void)out_size;
    const float* x   = (const float*)d_in[0];
    const float* U   = (const float*)d_in[1];
    const float* S   = (const float*)d_in[2];
    const float* V   = (const float*)d_in[3];
    const float* dlt = (const float*)d_in[4];
    const float* Q1  = (const float*)d_in[5];
    const float* Q2  = (const float*)d_in[6];
    const float* Q3  = (const float*)d_in[7];
    float* out = (float*)d_out;

    __nv_bfloat16 *xhi, *xlo, *VThi, *VTlo, *Ushi, *Uslo, *Wthi, *Wtlo;
    float *W0, *W1;
    cudaGetSymbolAddress((void**)&xhi,  g_xhi);
    cudaGetSymbolAddress((void**)&xlo,  g_xlo);
    cudaGetSymbolAddress((void**)&VThi, g_VThi);
    cudaGetSymbolAddress((void**)&VTlo, g_VTlo);
    cudaGetSymbolAddress((void**)&Ushi, g_Ushi);
    cudaGetSymbolAddress((void**)&Uslo, g_Uslo);
    cudaGetSymbolAddress((void**)&Wthi, g_Wthi);
    cudaGetSymbolAddress((void**)&Wtlo, g_Wtlo);
    cudaGetSymbolAddress((void**)&W0,   g_W0);
    cudaGetSymbolAddress((void**)&W1,   g_W1);

    cudaFuncSetAttribute(mma_gemm_split,
                         cudaFuncAttributeMaxDynamicSharedMemorySize, GEMM_SMEM);

    // 1) x -> x_hi/x_lo
    {
        size_t n4 = (size_t)SEQ_M * IN_F / 4;
        split_scale_kernel<<<(unsigned)(n4 / 256), 256>>>(
            x, nullptr, nullptr, xhi, xlo, n4, IN_F);
    }
    // 2) V [k][d] -> VT [d][k] hi/lo
    transpose_split_kernel<<<dim3(IN_F / 32, IN_F / 32), dim3(32, 8)>>>(
        V, VThi, VTlo, IN_F, IN_F);
    // 3) U[o][k] * relu(S[k]+delta[k]) -> Us hi/lo
    {
        size_t n4 = (size_t)IN_F * IN_F / 4;
        split_scale_kernel<<<(unsigned)(n4 / 256), 256>>>(
            U, S, dlt, Ushi, Uslo, n4, IN_F);
    }
    // 4) W^T[d][o] = sum_k V[k][d] * U[o][k]*s(k)
    mma_gemm_split<<<dim3(IN_F / 128, IN_F / 128), 256, GEMM_SMEM>>>(
        VThi, VTlo, Ushi, Uslo, W0, IN_F, IN_F, IN_F);

    // 5) Kronecker: contract j3 (Q3), j2 (Q2), j1 (Q1); d=(j1*16+j2)*12+j3
    kron_stage_kernel<<<dim3(IN_F / 256, 256), 256>>>(W0, W1, Q3, 12, 1);
    kron_stage_kernel<<<dim3(IN_F / 256, 192), 256>>>(W1, W0, Q2, 16, 12);
    kron_stage_kernel<<<dim3(IN_F / 256, 192), 256>>>(W0, W1, Q1, 16, 192);

    // 6) W_t [d][o] -> Wt [o][d] hi/lo
    transpose_split_kernel<<<dim3(IN_F / 32, IN_F / 32), dim3(32, 8)>>>(
        W1, Wthi, Wtlo, IN_F, IN_F);

    // 7) out[m][o] = sum_d x[m][d] * W_t[d][o]
    mma_gemm_split<<<dim3(IN_F / 128, SEQ_M / 128), 256, GEMM_SMEM>>>(
        xhi, xlo, Wthi, Wtlo, out, SEQ_M, IN_F, IN_F);
}

// round 8
// speedup vs baseline: 5.7510x; 1.3930x over previous
#include <cuda_runtime.h>
#include <cuda_fp16.h>
#include <cstdint>
#include <cstddef>

// ---------------------------------------------------------------------------
// InjectedSODA_SVD: out = x @ ( (Q1⊗Q2⊗Q3) @ ((U*relu(S+delta)) @ V)^T )
//
// fp16 asymmetric split + warp-level mma.sync (m16n8k16, f16 -> f32):
//   A @ B ≈ Ah @ Bhi + Ah @ Blo      (A plain fp16; B split hi/lo)
// Error ~ rms(Alo)/rms(A) ≈ 2^-11 ≈ 2e-4 (random-signed, cancels in K-sum).
// Operands pre-scaled x256 at split, epilogue divides (avoids fp16 subnormals).
//
// Pipeline:
//   1) x -> xh fp16                               (convert)
//   2) V -> VTh [d,k] fp16 (x256)                 (transpose+convert)
//   3) U*relu(S+delta) -> Us hi/lo (x256)         (scale+split)
//   4) W^T[d,o] = VTh @ Us^T      /65536          (warp-MMA GEMM, fp32 out)
//   5) kron stages Q3,Q2,Q1 (fp32)
//   6) W_t[d,o] -> Wt hi/lo [o,d] (x256)          (transpose+split)
//   7) out[m,o] = xh @ Wt^T       /256            (warp-MMA GEMM)
// ---------------------------------------------------------------------------

#define IN_F   3072
#define SEQ_M  16384

// ---------------- scratch (device globals; allocation is forbidden) --------
__device__ __align__(1024) __half g_xh  [(size_t)SEQ_M * IN_F];
__device__ __align__(1024) __half g_VTh [(size_t)IN_F * IN_F];
__device__ __align__(1024) __half g_Ushi[(size_t)IN_F * IN_F];
__device__ __align__(1024) __half g_Uslo[(size_t)IN_F * IN_F];
__device__ __align__(1024) __half g_Wthi[(size_t)IN_F * IN_F];
__device__ __align__(1024) __half g_Wtlo[(size_t)IN_F * IN_F];
__device__ __align__(1024) float  g_W0[(size_t)IN_F * IN_F];
__device__ __align__(1024) float  g_W1[(size_t)IN_F * IN_F];

// ---------------- PTX helpers (base-target only) ----------------------------
__device__ __forceinline__ uint32_t smem_u32(const void* p) {
    uint32_t a;
    asm("{ .reg .u64 t; cvta.to.shared.u64 t, %1; cvt.u32.u64 %0, t; }"
        : "=r"(a) : "l"(p));
    return a;
}
__device__ __forceinline__ uint32_t swz128(uint32_t o) {
    return o ^ ((o >> 3) & 0x70);
}
__device__ __forceinline__ void cp16(uint32_t dst, const void* src) {
    asm volatile("cp.async.cg.shared.global [%0], [%1], 16;"
                 :: "r"(dst), "l"(src));
}
__device__ __forceinline__ void ldsm4(uint32_t* r, uint32_t addr) {
    asm volatile("ldmatrix.sync.aligned.m8n8.x4.shared.b16 {%0,%1,%2,%3}, [%4];"
                 : "=r"(r[0]), "=r"(r[1]), "=r"(r[2]), "=r"(r[3])
                 : "r"(addr));
}
__device__ __forceinline__ void mma16816(float* c, const uint32_t* a,
                                         const uint32_t* b) {
    asm volatile(
        "mma.sync.aligned.m16n8k16.row.col.f32.f16.f16.f32 "
        "{%0,%1,%2,%3}, {%4,%5,%6,%7}, {%8,%9}, {%0,%1,%2,%3};"
        : "+f"(c[0]), "+f"(c[1]), "+f"(c[2]), "+f"(c[3])
        : "r"(a[0]), "r"(a[1]), "r"(a[2]), "r"(a[3]), "r"(b[0]), "r"(b[1]));
}

// ---------------- split helper ----------------------------------------------
__device__ __forceinline__ void split_h(float v, __half& h, __half& l) {
    h = __float2half_rn(v);
    l = __float2half_rn(v - __half2float(h));
}

// ---------------------------------------------------------------------------
// scale(+optional per-col relu(S+D)) then fp16 split (lo optional):
// hi[i] = fp16(v*scale), lo[i] = fp16(v*scale - hi[i])
// ---------------------------------------------------------------------------
__global__ void split_scale_kernel(const float* __restrict__ in,
                                   const float* __restrict__ S,
                                   const float* __restrict__ D,
                                   __half* __restrict__ hi,
                                   __half* __restrict__ lo,
                                   size_t n4, int cols, float scale)
{
    size_t i = (size_t)blockIdx.x * blockDim.x + threadIdx.x;
    if (i >= n4) return;
    float4 v = ((const float4*)in)[i];
    if (S) {
        int c = (int)((i * 4) % (size_t)cols);
        v.x *= fmaxf(S[c + 0] + D[c + 0], 0.0f);
        v.y *= fmaxf(S[c + 1] + D[c + 1], 0.0f);
        v.z *= fmaxf(S[c + 2] + D[c + 2], 0.0f);
        v.w *= fmaxf(S[c + 3] + D[c + 3], 0.0f);
    }
    v.x *= scale; v.y *= scale; v.z *= scale; v.w *= scale;
    __half h[4], l[4];
    split_h(v.x, h[0], l[0]);
    split_h(v.y, h[1], l[1]);
    split_h(v.z, h[2], l[2]);
    split_h(v.w, h[3], l[3]);
    ((__half2*)hi)[i * 2 + 0] = __halves2half2(h[0], h[1]);
    ((__half2*)hi)[i * 2 + 1] = __halves2half2(h[2], h[3]);
    if (lo) {
        ((__half2*)lo)[i * 2 + 0] = __halves2half2(l[0], l[1]);
        ((__half2*)lo)[i * 2 + 1] = __halves2half2(l[2], l[3]);
    }
}

// ---------------------------------------------------------------------------
// transpose + scale + split (lo optional): in [NJ][NI] f32 -> [NI][NJ] fp16
// ---------------------------------------------------------------------------
__global__ void transpose_split_kernel(const float* __restrict__ in,
                                       __half* __restrict__ hi,
                                       __half* __restrict__ lo,
                                       int NJ, int NI, float scale)
{
    __shared__ float t[32][33];
    const int i0 = blockIdx.y * 32;
    const int j0 = blockIdx.x * 32;
    const int x = threadIdx.x, y = threadIdx.y;
#pragma unroll
    for (int r = 0; r < 4; r++)
        t[y + 8 * r][x] = in[(size_t)(j0 + y + 8 * r) * NI + (i0 + x)];
    __syncthreads();
#pragma unroll
    for (int r = 0; r < 4; r++) {
        const int i = i0 + y + 8 * r;
        __half h, l;
        split_h(t[x][y + 8 * r] * scale, h, l);
        hi[(size_t)i * NJ + (j0 + x)] = h;
        if (lo) lo[(size_t)i * NJ + (j0 + x)] = l;
    }
}

// ---------------------------------------------------------------------------
// Kronecker mode contraction (fp32; unchanged from passing kernel)
// ---------------------------------------------------------------------------
__global__ void kron_stage_kernel(const float* __restrict__ in,
                                  float* __restrict__ out,
                                  const float* __restrict__ Q,
                                  int R, int I)
{
    __shared__ float sQ[256];
    __shared__ float sIn[16][256];
    const int tid = threadIdx.x;
    const int o = blockIdx.x * 256 + tid;
    const int a = blockIdx.y / I;
    const int c = blockIdx.y % I;
    if (tid < R * R) sQ[tid] = Q[tid];
    const int rbase = a * R * I + c;
    for (int j = 0; j < R; j++)
        sIn[j][tid] = in[(size_t)(rbase + j * I) * IN_F + o];
    __syncthreads();
    for (int i = 0; i < R; i++) {
        float acc = 0.0f;
        for (int j = 0; j < R; j++)
            acc = fmaf(sQ[i * R + j], sIn[j][tid], acc);
        out[(size_t)(rbase + i * I) * IN_F + o] = acc;
    }
}

// ---------------------------------------------------------------------------
// Warp-MMA 2-term fp16 GEMM: C[m][n] = out_scale * sum_k Ah[m][k]*(Bh+Bl)[n][k]
// Block 128x128, K-chunk 64 (128B swizzled rows), 4-stage cp.async pipeline,
// ONE __syncthreads per chunk; loads for chunk kc+3 issued before compute kc.
// 8 warps (2M x 4N), warp tile 64x32. M,N,K multiples of 128/128/64.
// ---------------------------------------------------------------------------
#define GKCH       64
#define TILE_OP_B  16384                   // 128 rows x 128 bytes
#define STAGE_B    (3 * TILE_OP_B)         // Ah, Bh, Bl = 48 KB
#define NSTAGE     4
#define SOF_AH     0
#define SOF_BH     16384
#define SOF_BL     32768
#define GEMM_SMEM  (NSTAGE * STAGE_B + 1024)   // 193 KB

__device__ __forceinline__ void load_tiles(uint32_t sb,
                                           const char* pAh, const char* pBh,
                                           const char* pBl,
                                           size_t ldb, size_t gbase, int tid)
{
#pragma unroll
    for (int i = 0; i < 4; i++) {
        int idx = tid + i * 256;
        int row = idx >> 3;
        uint32_t c16 = (uint32_t)(idx & 7) << 4;
        uint32_t so = swz128((uint32_t)row * 128u + c16);
        size_t go = (size_t)row * ldb + gbase + c16;
        cp16(sb + SOF_AH + so, pAh + go);
        cp16(sb + SOF_BH + so, pBh + go);
        cp16(sb + SOF_BL + so, pBl + go);
    }
}

__global__ __launch_bounds__(256, 1)
void mma_gemm2(const __half* __restrict__ Ah,
               const __half* __restrict__ Bh,
               const __half* __restrict__ Bl,
               float* __restrict__ C, int M, int N, int K, float out_scale)
{
    extern __shared__ char dynsmem[];
    const int tid = threadIdx.x;
    const uint32_t smem = (smem_u32(dynsmem) + 1023u) & ~1023u;

    const int w = tid >> 5, lane = tid & 31;
    const int m0 = (w >> 2) * 64;          // 2 M-slabs
    const int n0 = (w & 3) * 32;           // 4 N-slabs

    // ldmatrix lane patterns
    const int rowA  = lane & 15;
    const uint32_t kselA = (uint32_t)(lane >> 4) << 4;       // 0 or 16
    const int rowB  = (lane & 7) + ((lane >> 4) << 3);
    const uint32_t kselB = (uint32_t)((lane >> 3) & 1) << 4; // 0 or 16

    const size_t ldb = (size_t)K * 2;
    const char* pAh = (const char*)Ah + (size_t)blockIdx.y * 128 * ldb;
    const char* pBh = (const char*)Bh + (size_t)blockIdx.x * 128 * ldb;
    const char* pBl = (const char*)Bl + (size_t)blockIdx.x * 128 * ldb;

    float acc[4][4][4];
#pragma unroll
    for (int a = 0; a < 4; a++)
#pragma unroll
        for (int b = 0; b < 4; b++)
#pragma unroll
            for (int c = 0; c < 4; c++) acc[a][b][c] = 0.0f;

    const int KT = K / GKCH;

    // prologue: stages 0..2
#pragma unroll
    for (int c = 0; c < NSTAGE - 1; c++) {
        load_tiles(smem + c * STAGE_B, pAh, pBh, pBl, ldb,
                   (size_t)c * (GKCH * 2), tid);
        asm volatile("cp.async.commit_group;" ::: "memory");
    }

    for (int kc = 0; kc < KT; kc++) {
        const uint32_t sb = smem + (uint32_t)(kc & (NSTAGE - 1)) * STAGE_B;

        // chunk kc resident (<= NSTAGE-2 groups still in flight)
        asm volatile("cp.async.wait_group %0;" :: "n"(NSTAGE - 2) : "memory");
        __syncthreads();   // all warps done with chunk kc-1's buffer

        // prefetch chunk kc+3 into the buffer retired at kc-1 (overlaps MMA)
        if (kc + NSTAGE - 1 < KT)
            load_tiles(smem + (uint32_t)((kc + NSTAGE - 1) & (NSTAGE - 1)) * STAGE_B,
                       pAh, pBh, pBl, ldb,
                       (size_t)(kc + NSTAGE - 1) * (GKCH * 2), tid);
        asm volatile("cp.async.commit_group;" ::: "memory");

#pragma unroll
        for (int kk = 0; kk < 4; kk++) {
            const uint32_t kb = (uint32_t)kk * 32;
            uint32_t ah[4][4], bh[2][4], bl[2][4];
#pragma unroll
            for (int mi = 0; mi < 4; mi++) {
                uint32_t off = swz128((uint32_t)(m0 + mi * 16 + rowA) * 128u
                                      + kb + kselA);
                ldsm4(ah[mi], sb + SOF_AH + off);
            }
#pragma unroll
            for (int j = 0; j < 2; j++) {
                uint32_t off = swz128((uint32_t)(n0 + j * 16 + rowB) * 128u
                                      + kb + kselB);
                ldsm4(bh[j], sb + SOF_BH + off);
                ldsm4(bl[j], sb + SOF_BL + off);
            }
            // term 1: Ah * Bhi
#pragma unroll
            for (int mi = 0; mi < 4; mi++)
#pragma unroll
                for (int ni = 0; ni < 4; ni++)
                    mma16816(acc[mi][ni], ah[mi], &bh[ni >> 1][(ni & 1) * 2]);
            // term 2: Ah * Blo
#pragma unroll
            for (int mi = 0; mi < 4; mi++)
#pragma unroll
                for (int ni = 0; ni < 4; ni++)
                    mma16816(acc[mi][ni], ah[mi], &bl[ni >> 1][(ni & 1) * 2]);
        }
    }

    // epilogue: scale + direct f32 stores
    const int g = lane >> 2, t2 = (lane & 3) * 2;
    const size_t rbase = (size_t)blockIdx.y * 128 + m0;
    const size_t cbase = (size_t)blockIdx.x * 128 + n0;
#pragma unroll
    for (int mi = 0; mi < 4; mi++) {
#pragma unroll
        for (int ni = 0; ni < 4; ni++) {
            float* p0 = C + (rbase + mi * 16 + g) * (size_t)N
                          + cbase + ni * 8 + t2;
            float* p1 = p0 + 8 * (size_t)N;
            *(float2*)p0 = make_float2(acc[mi][ni][0] * out_scale,
                                       acc[mi][ni][1] * out_scale);
            *(float2*)p1 = make_float2(acc[mi][ni][2] * out_scale,
                                       acc[mi][ni][3] * out_scale);
        }
    }
}

// ---------------------------------------------------------------------------
// Launch
// ---------------------------------------------------------------------------
extern "C" void kernel_launch(void* const* d_in, const int* in_sizes, int n_in,
                              void* d_out, int out_size)
{
    (void)in_sizes; (void)n_in; (void)out_size;
    const float* x   = (const float*)d_in[0];
    const float* U   = (const float*)d_in[1];
    const float* S   = (const float*)d_in[2];
    const float* V   = (const float*)d_in[3];
    const float* dlt = (const float*)d_in[4];
    const float* Q1  = (const float*)d_in[5];
    const float* Q2  = (const float*)d_in[6];
    const float* Q3  = (const float*)d_in[7];
    float* out = (float*)d_out;

    __half *xh, *VTh, *Ushi, *Uslo, *Wthi, *Wtlo;
    float *W0, *W1;
    cudaGetSymbolAddress((void**)&xh,   g_xh);
    cudaGetSymbolAddress((void**)&VTh,  g_VTh);
    cudaGetSymbolAddress((void**)&Ushi, g_Ushi);
    cudaGetSymbolAddress((void**)&Uslo, g_Uslo);
    cudaGetSymbolAddress((void**)&Wthi, g_Wthi);
    cudaGetSymbolAddress((void**)&Wtlo, g_Wtlo);
    cudaGetSymbolAddress((void**)&W0,   g_W0);
    cudaGetSymbolAddress((void**)&W1,   g_W1);

    cudaFuncSetAttribute(mma_gemm2,
                         cudaFuncAttributeMaxDynamicSharedMemorySize, GEMM_SMEM);

    // 1) x -> xh (fp16, unscaled; hi only)
    {
        size_t n4 = (size_t)SEQ_M * IN_F / 4;
        split_scale_kernel<<<(unsigned)(n4 / 256), 256>>>(
            x, nullptr, nullptr, xh, nullptr, n4, IN_F, 1.0f);
    }
    // 2) V [k][d] -> VTh [d][k] (x256, hi only)
    transpose_split_kernel<<<dim3(IN_F / 32, IN_F / 32), dim3(32, 8)>>>(
        V, VTh, nullptr, IN_F, IN_F, 256.0f);
    // 3) U[o][k]*relu(S[k]+delta[k]) -> Us hi/lo (x256)
    {
        size_t n4 = (size_t)IN_F * IN_F / 4;
        split_scale_kernel<<<(unsigned)(n4 / 256), 256>>>(
            U, S, dlt, Ushi, Uslo, n4, IN_F, 256.0f);
    }
    // 4) W^T[d][o] = (VTh @ Us^T) / 65536
    mma_gemm2<<<dim3(IN_F / 128, IN_F / 128), 256, GEMM_SMEM>>>(
        VTh, Ushi, Uslo, W0, IN_F, IN_F, IN_F, 1.0f / 65536.0f);

    // 5) Kronecker: contract j3 (Q3), j2 (Q2), j1 (Q1); d=(j1*16+j2)*12+j3
    kron_stage_kernel<<<dim3(IN_F / 256, 256), 256>>>(W0, W1, Q3, 12, 1);
    kron_stage_kernel<<<dim3(IN_F / 256, 192), 256>>>(W1, W0, Q2, 16, 12);
    kron_stage_kernel<<<dim3(IN_F / 256, 192), 256>>>(W0, W1, Q1, 16, 192);

    // 6) W_t [d][o] -> Wt [o][d] hi/lo (x256)
    transpose_split_kernel<<<dim3(IN_F / 32, IN_F / 32), dim3(32, 8)>>>(
        W1, Wthi, Wtlo, IN_F, IN_F, 256.0f);

    // 7) out[m][o] = (xh @ Wt^T) / 256
    mma_gemm2<<<dim3(IN_F / 128, SEQ_M / 128), 256, GEMM_SMEM>>>(
        xh, Wthi, Wtlo, out, SEQ_M, IN_F, IN_F, 1.0f / 256.0f);
}

// round 10
// speedup vs baseline: 9.7003x; 1.6867x over previous
#include <cuda_runtime.h>
#include <cuda_fp16.h>
#include <cstdint>
#include <cstddef>

// ---------------------------------------------------------------------------
// InjectedSODA_SVD: out = x @ ( (Q1⊗Q2⊗Q3) @ ((U*relu(S+delta)) @ V)^T )
//
// Pure fp16 1-term warp-MMA (m16n8k16 f16->f32). Error budget: four fp16
// rounding sources (V, U, x, W_t), each ~2e-4, quadrature total ~4e-4 < 1e-3.
// Weight-path operands pre-scaled x256 (power of two, exact) so W_t elements
// (~2e-5) stay out of the fp16 subnormal range; epilogues divide it back out.
//
// Pipeline:
//   1) x -> xh fp16                               (convert)
//   2) V -> VTh [d,k] fp16 (x256)                 (transpose+convert)
//   3) U*relu(S+delta) -> Ush (x256)              (scale+convert)
//   4) W^T[d,o] = VTh @ Ush^T     /65536          (warp-MMA GEMM, fp32 out)
//   5) kron stages Q3,Q2,Q1 (fp32)
//   6) W_t[d,o] -> Wth [o,d] (x256)               (transpose+convert)
//   7) out[m,o] = xh @ Wth^T      /256            (warp-MMA GEMM)
//
// GEMM: block 128x256, 8 warps (2M x 4N) with 64x64 warp tiles, K-chunk 64,
// 4-stage cp.async pipeline, one __syncthreads per chunk, prefetch issued
// before compute of the current chunk.
//
// (R9 bench failed with cudaErrorSystemNotReady at harness init — infra
//  flake, not a kernel property. Resubmitting for a clean measurement.)
// ---------------------------------------------------------------------------

#define IN_F   3072
#define SEQ_M  16384

// ---------------- scratch (device globals; allocation is forbidden) --------
__device__ __align__(1024) __half g_xh [(size_t)SEQ_M * IN_F];
__device__ __align__(1024) __half g_VTh[(size_t)IN_F * IN_F];
__device__ __align__(1024) __half g_Ush[(size_t)IN_F * IN_F];
__device__ __align__(1024) __half g_Wth[(size_t)IN_F * IN_F];
__device__ __align__(1024) float  g_W0[(size_t)IN_F * IN_F];
__device__ __align__(1024) float  g_W1[(size_t)IN_F * IN_F];

// ---------------- PTX helpers (base-target only) ----------------------------
__device__ __forceinline__ uint32_t smem_u32(const void* p) {
    uint32_t a;
    asm("{ .reg .u64 t; cvta.to.shared.u64 t, %1; cvt.u32.u64 %0, t; }"
        : "=r"(a) : "l"(p));
    return a;
}
__device__ __forceinline__ uint32_t swz128(uint32_t o) {
    return o ^ ((o >> 3) & 0x70);
}
__device__ __forceinline__ void cp16(uint32_t dst, const void* src) {
    asm volatile("cp.async.cg.shared.global [%0], [%1], 16;"
                 :: "r"(dst), "l"(src));
}
__device__ __forceinline__ void ldsm4(uint32_t* r, uint32_t addr) {
    asm volatile("ldmatrix.sync.aligned.m8n8.x4.shared.b16 {%0,%1,%2,%3}, [%4];"
                 : "=r"(r[0]), "=r"(r[1]), "=r"(r[2]), "=r"(r[3])
                 : "r"(addr));
}
__device__ __forceinline__ void mma16816(float* c, const uint32_t* a,
                                         const uint32_t* b) {
    asm volatile(
        "mma.sync.aligned.m16n8k16.row.col.f32.f16.f16.f32 "
        "{%0,%1,%2,%3}, {%4,%5,%6,%7}, {%8,%9}, {%0,%1,%2,%3};"
        : "+f"(c[0]), "+f"(c[1]), "+f"(c[2]), "+f"(c[3])
        : "r"(a[0]), "r"(a[1]), "r"(a[2]), "r"(a[3]), "r"(b[0]), "r"(b[1]));
}

// ---------------------------------------------------------------------------
// scale(+optional per-col relu(S+D)) then fp16 convert
// ---------------------------------------------------------------------------
__global__ void conv_scale_kernel(const float* __restrict__ in,
                                  const float* __restrict__ S,
                                  const float* __restrict__ D,
                                  __half* __restrict__ out16,
                                  size_t n4, int cols, float scale)
{
    size_t i = (size_t)blockIdx.x * blockDim.x + threadIdx.x;
    if (i >= n4) return;
    float4 v = ((const float4*)in)[i];
    if (S) {
        int c = (int)((i * 4) % (size_t)cols);
        v.x *= fmaxf(S[c + 0] + D[c + 0], 0.0f);
        v.y *= fmaxf(S[c + 1] + D[c + 1], 0.0f);
        v.z *= fmaxf(S[c + 2] + D[c + 2], 0.0f);
        v.w *= fmaxf(S[c + 3] + D[c + 3], 0.0f);
    }
    v.x *= scale; v.y *= scale; v.z *= scale; v.w *= scale;
    ((__half2*)out16)[i * 2 + 0] =
        __halves2half2(__float2half_rn(v.x), __float2half_rn(v.y));
    ((__half2*)out16)[i * 2 + 1] =
        __halves2half2(__float2half_rn(v.z), __float2half_rn(v.w));
}

// ---------------------------------------------------------------------------
// transpose + scale + fp16 convert: in [NJ][NI] f32 -> [NI][NJ] fp16
// ---------------------------------------------------------------------------
__global__ void transpose_conv_kernel(const float* __restrict__ in,
                                      __half* __restrict__ out16,
                                      int NJ, int NI, float scale)
{
    __shared__ float t[32][33];
    const int i0 = blockIdx.y * 32;
    const int j0 = blockIdx.x * 32;
    const int x = threadIdx.x, y = threadIdx.y;
#pragma unroll
    for (int r = 0; r < 4; r++)
        t[y + 8 * r][x] = in[(size_t)(j0 + y + 8 * r) * NI + (i0 + x)];
    __syncthreads();
#pragma unroll
    for (int r = 0; r < 4; r++) {
        const int i = i0 + y + 8 * r;
        out16[(size_t)i * NJ + (j0 + x)] =
            __float2half_rn(t[x][y + 8 * r] * scale);
    }
}

// ---------------------------------------------------------------------------
// Kronecker mode contraction (fp32; unchanged from passing kernel)
// ---------------------------------------------------------------------------
__global__ void kron_stage_kernel(const float* __restrict__ in,
                                  float* __restrict__ out,
                                  const float* __restrict__ Q,
                                  int R, int I)
{
    __shared__ float sQ[256];
    __shared__ float sIn[16][256];
    const int tid = threadIdx.x;
    const int o = blockIdx.x * 256 + tid;
    const int a = blockIdx.y / I;
    const int c = blockIdx.y % I;
    if (tid < R * R) sQ[tid] = Q[tid];
    const int rbase = a * R * I + c;
    for (int j = 0; j < R; j++)
        sIn[j][tid] = in[(size_t)(rbase + j * I) * IN_F + o];
    __syncthreads();
    for (int i = 0; i < R; i++) {
        float acc = 0.0f;
        for (int j = 0; j < R; j++)
            acc = fmaf(sQ[i * R + j], sIn[j][tid], acc);
        out[(size_t)(rbase + i * I) * IN_F + o] = acc;
    }
}

// ---------------------------------------------------------------------------
// Warp-MMA 1-term fp16 GEMM: C[m][n] = out_scale * sum_k A[m][k]*B[n][k]
// Block 128x256, K-chunk 64 (128B swizzled rows), 4-stage cp.async pipeline.
// 8 warps (2M x 4N), warp tile 64x64. M,N,K multiples of 128/256/64.
// ---------------------------------------------------------------------------
#define GKCH       64
#define SOF_A      0
#define SOF_B      16384                   // A: 128 rows x 128 B
#define STAGE_B    49152                   // + B: 256 rows x 128 B = 48 KB
#define NSTAGE     4
#define GEMM_SMEM  (NSTAGE * STAGE_B + 1024)   // ~193 KB

__device__ __forceinline__ void load_tiles(uint32_t sb,
                                           const char* pA, const char* pB,
                                           size_t ldb, size_t gbase, int tid)
{
    // A tile: 1024 x 16B
#pragma unroll
    for (int i = 0; i < 4; i++) {
        int idx = tid + i * 256;
        int row = idx >> 3;
        uint32_t c16 = (uint32_t)(idx & 7) << 4;
        uint32_t so = swz128((uint32_t)row * 128u + c16);
        cp16(sb + SOF_A + so, pA + (size_t)row * ldb + gbase + c16);
    }
    // B tile: 2048 x 16B
#pragma unroll
    for (int i = 0; i < 8; i++) {
        int idx = tid + i * 256;
        int row = idx >> 3;
        uint32_t c16 = (uint32_t)(idx & 7) << 4;
        uint32_t so = swz128((uint32_t)row * 128u + c16);
        cp16(sb + SOF_B + so, pB + (size_t)row * ldb + gbase + c16);
    }
}

__global__ __launch_bounds__(256, 1)
void mma_gemm1(const __half* __restrict__ A,
               const __half* __restrict__ B,
               float* __restrict__ C, int M, int N, int K, float out_scale)
{
    extern __shared__ char dynsmem[];
    const int tid = threadIdx.x;
    const uint32_t smem = (smem_u32(dynsmem) + 1023u) & ~1023u;

    const int w = tid >> 5, lane = tid & 31;
    const int m0 = (w >> 2) * 64;          // 2 M-slabs of 64
    const int n0 = (w & 3) * 64;           // 4 N-slabs of 64

    // ldmatrix lane patterns
    const int rowA  = lane & 15;
    const uint32_t kselA = (uint32_t)(lane >> 4) << 4;       // 0 or 16
    const int rowB  = (lane & 7) + ((lane >> 4) << 3);
    const uint32_t kselB = (uint32_t)((lane >> 3) & 1) << 4; // 0 or 16

    const size_t ldb = (size_t)K * 2;
    const char* pA = (const char*)A + (size_t)blockIdx.y * 128 * ldb;
    const char* pB = (const char*)B + (size_t)blockIdx.x * 256 * ldb;

    float acc[4][8][4];
#pragma unroll
    for (int a = 0; a < 4; a++)
#pragma unroll
        for (int b = 0; b < 8; b++)
#pragma unroll
            for (int c = 0; c < 4; c++) acc[a][b][c] = 0.0f;

    const int KT = K / GKCH;

    // prologue: stages 0..2
#pragma unroll
    for (int c = 0; c < NSTAGE - 1; c++) {
        load_tiles(smem + c * STAGE_B, pA, pB, ldb, (size_t)c * (GKCH * 2), tid);
        asm volatile("cp.async.commit_group;" ::: "memory");
    }

    for (int kc = 0; kc < KT; kc++) {
        const uint32_t sb = smem + (uint32_t)(kc & (NSTAGE - 1)) * STAGE_B;

        // chunk kc resident (<= NSTAGE-2 groups still in flight)
        asm volatile("cp.async.wait_group %0;" :: "n"(NSTAGE - 2) : "memory");
        __syncthreads();   // all warps done with the buffer retired at kc-1

        // prefetch chunk kc+3 (overlaps with the MMA work below)
        if (kc + NSTAGE - 1 < KT)
            load_tiles(smem + (uint32_t)((kc + NSTAGE - 1) & (NSTAGE - 1)) * STAGE_B,
                       pA, pB, ldb, (size_t)(kc + NSTAGE - 1) * (GKCH * 2), tid);
        asm volatile("cp.async.commit_group;" ::: "memory");

#pragma unroll
        for (int kk = 0; kk < 4; kk++) {
            const uint32_t kb = (uint32_t)kk * 32;
            uint32_t af[4][4], bf[4][4];
#pragma unroll
            for (int mi = 0; mi < 4; mi++) {
                uint32_t off = swz128((uint32_t)(m0 + mi * 16 + rowA) * 128u
                                      + kb + kselA);
                ldsm4(af[mi], sb + SOF_A + off);
            }
#pragma unroll
            for (int j = 0; j < 4; j++) {
                uint32_t off = swz128((uint32_t)(n0 + j * 16 + rowB) * 128u
                                      + kb + kselB);
                ldsm4(bf[j], sb + SOF_B + off);
            }
#pragma unroll
            for (int mi = 0; mi < 4; mi++)
#pragma unroll
                for (int ni = 0; ni < 8; ni++)
                    mma16816(acc[mi][ni], af[mi], &bf[ni >> 1][(ni & 1) * 2]);
        }
    }

    // epilogue: scale + direct f32 stores
    const int g = lane >> 2, t2 = (lane & 3) * 2;
    const size_t rbase = (size_t)blockIdx.y * 128 + m0;
    const size_t cbase = (size_t)blockIdx.x * 256 + n0;
#pragma unroll
    for (int mi = 0; mi < 4; mi++) {
#pragma unroll
        for (int ni = 0; ni < 8; ni++) {
            float* p0 = C + (rbase + mi * 16 + g) * (size_t)N
                          + cbase + ni * 8 + t2;
            float* p1 = p0 + 8 * (size_t)N;
            *(float2*)p0 = make_float2(acc[mi][ni][0] * out_scale,
                                       acc[mi][ni][1] * out_scale);
            *(float2*)p1 = make_float2(acc[mi][ni][2] * out_scale,
                                       acc[mi][ni][3] * out_scale);
        }
    }
}

// ---------------------------------------------------------------------------
// Launch
// ---------------------------------------------------------------------------
extern "C" void kernel_launch(void* const* d_in, const int* in_sizes, int n_in,
                              void* d_out, int out_size)
{
    (void)in_sizes; (void)n_in; (void)out_size;
    const float* x   = (const float*)d_in[0];
    const float* U   = (const float*)d_in[1];
    const float* S   = (const float*)d_in[2];
    const float* V   = (const float*)d_in[3];
    const float* dlt = (const float*)d_in[4];
    const float* Q1  = (const float*)d_in[5];
    const float* Q2  = (const float*)d_in[6];
    const float* Q3  = (const float*)d_in[7];
    float* out = (float*)d_out;

    __half *xh, *VTh, *Ush, *Wth;
    float *W0, *W1;
    cudaGetSymbolAddress((void**)&xh,  g_xh);
    cudaGetSymbolAddress((void**)&VTh, g_VTh);
    cudaGetSymbolAddress((void**)&Ush, g_Ush);
    cudaGetSymbolAddress((void**)&Wth, g_Wth);
    cudaGetSymbolAddress((void**)&W0,  g_W0);
    cudaGetSymbolAddress((void**)&W1,  g_W1);

    cudaFuncSetAttribute(mma_gemm1,
                         cudaFuncAttributeMaxDynamicSharedMemorySize, GEMM_SMEM);

    // 1) x -> xh (fp16, unscaled)
    {
        size_t n4 = (size_t)SEQ_M * IN_F / 4;
        conv_scale_kernel<<<(unsigned)(n4 / 256), 256>>>(
            x, nullptr, nullptr, xh, n4, IN_F, 1.0f);
    }
    // 2) V [k][d] -> VTh [d][k] (x256)
    transpose_conv_kernel<<<dim3(IN_F / 32, IN_F / 32), dim3(32, 8)>>>(
        V, VTh, IN_F, IN_F, 256.0f);
    // 3) U[o][k]*relu(S[k]+delta[k]) -> Ush (x256)
    {
        size_t n4 = (size_t)IN_F * IN_F / 4;
        conv_scale_kernel<<<(unsigned)(n4 / 256), 256>>>(
            U, S, dlt, Ush, n4, IN_F, 256.0f);
    }
    // 4) W^T[d][o] = (VTh @ Ush^T) / 65536
    mma_gemm1<<<dim3(IN_F / 256, IN_F / 128), 256, GEMM_SMEM>>>(
        VTh, Ush, W0, IN_F, IN_F, IN_F, 1.0f / 65536.0f);

    // 5) Kronecker: contract j3 (Q3), j2 (Q2), j1 (Q1); d=(j1*16+j2)*12+j3
    kron_stage_kernel<<<dim3(IN_F / 256, 256), 256>>>(W0, W1, Q3, 12, 1);
    kron_stage_kernel<<<dim3(IN_F / 256, 192), 256>>>(W1, W0, Q2, 16, 12);
    kron_stage_kernel<<<dim3(IN_F / 256, 192), 256>>>(W0, W1, Q1, 16, 192);

    // 6) W_t [d][o] -> Wth [o][d] (x256)
    transpose_conv_kernel<<<dim3(IN_F / 32, IN_F / 32), dim3(32, 8)>>>(
        W1, Wth, IN_F, IN_F, 256.0f);

    // 7) out[m][o] = (xh @ Wth^T) / 256
    mma_gemm1<<<dim3(IN_F / 256, SEQ_M / 128), 256, GEMM_SMEM>>>(
        xh, Wth, out, SEQ_M, IN_F, IN_F, 1.0f / 256.0f);
}

// round 11
// speedup vs baseline: 9.7575x; 1.0059x over previous
#include <cuda_runtime.h>
#include <cuda_fp16.h>
#include <cstdint>
#include <cstddef>

// ---------------------------------------------------------------------------
// InjectedSODA_SVD: out = x @ ( (Q1⊗Q2⊗Q3) @ ((U*relu(S+delta)) @ V)^T )
//
// Pure fp16 1-term warp-MMA (m16n8k16 f16->f32). Four fp16 rounding sources
// (V, U, x, W_t) ~2e-4 each, quadrature ~4e-4 < 1e-3 (measured 4.15e-4 @R10).
// Weight-path operands pre-scaled x256 (exact power of two) to avoid fp16
// subnormals in W_t; epilogues divide it back out.
//
// R11 change vs R10: GEMM goes 256->512 threads (16 warps, 2Mx8N, warp tile
// 64x32). 4 warps/SMSP doubles latency hiding; per-thread regs drop from 240
// to ~110 (acc 64 + frags 24), removing the pressure that serialized LDSM/HMMA.
// Block 128x256, K-chunk 64, 4-stage cp.async pipeline, one sync per chunk.
// ---------------------------------------------------------------------------

#define IN_F   3072
#define SEQ_M  16384

// ---------------- scratch (device globals; allocation is forbidden) --------
__device__ __align__(1024) __half g_xh [(size_t)SEQ_M * IN_F];
__device__ __align__(1024) __half g_VTh[(size_t)IN_F * IN_F];
__device__ __align__(1024) __half g_Ush[(size_t)IN_F * IN_F];
__device__ __align__(1024) __half g_Wth[(size_t)IN_F * IN_F];
__device__ __align__(1024) float  g_W0[(size_t)IN_F * IN_F];
__device__ __align__(1024) float  g_W1[(size_t)IN_F * IN_F];

// ---------------- PTX helpers (base-target only) ----------------------------
__device__ __forceinline__ uint32_t smem_u32(const void* p) {
    uint32_t a;
    asm("{ .reg .u64 t; cvta.to.shared.u64 t, %1; cvt.u32.u64 %0, t; }"
        : "=r"(a) : "l"(p));
    return a;
}
__device__ __forceinline__ uint32_t swz128(uint32_t o) {
    return o ^ ((o >> 3) & 0x70);
}
__device__ __forceinline__ void cp16(uint32_t dst, const void* src) {
    asm volatile("cp.async.cg.shared.global [%0], [%1], 16;"
                 :: "r"(dst), "l"(src));
}
__device__ __forceinline__ void ldsm4(uint32_t* r, uint32_t addr) {
    asm volatile("ldmatrix.sync.aligned.m8n8.x4.shared.b16 {%0,%1,%2,%3}, [%4];"
                 : "=r"(r[0]), "=r"(r[1]), "=r"(r[2]), "=r"(r[3])
                 : "r"(addr));
}
__device__ __forceinline__ void mma16816(float* c, const uint32_t* a,
                                         const uint32_t* b) {
    asm volatile(
        "mma.sync.aligned.m16n8k16.row.col.f32.f16.f16.f32 "
        "{%0,%1,%2,%3}, {%4,%5,%6,%7}, {%8,%9}, {%0,%1,%2,%3};"
        : "+f"(c[0]), "+f"(c[1]), "+f"(c[2]), "+f"(c[3])
        : "r"(a[0]), "r"(a[1]), "r"(a[2]), "r"(a[3]), "r"(b[0]), "r"(b[1]));
}

// ---------------------------------------------------------------------------
// scale(+optional per-col relu(S+D)) then fp16 convert
// ---------------------------------------------------------------------------
__global__ void conv_scale_kernel(const float* __restrict__ in,
                                  const float* __restrict__ S,
                                  const float* __restrict__ D,
                                  __half* __restrict__ out16,
                                  size_t n4, int cols, float scale)
{
    size_t i = (size_t)blockIdx.x * blockDim.x + threadIdx.x;
    if (i >= n4) return;
    float4 v = ((const float4*)in)[i];
    if (S) {
        int c = (int)((i * 4) % (size_t)cols);
        v.x *= fmaxf(S[c + 0] + D[c + 0], 0.0f);
        v.y *= fmaxf(S[c + 1] + D[c + 1], 0.0f);
        v.z *= fmaxf(S[c + 2] + D[c + 2], 0.0f);
        v.w *= fmaxf(S[c + 3] + D[c + 3], 0.0f);
    }
    v.x *= scale; v.y *= scale; v.z *= scale; v.w *= scale;
    ((__half2*)out16)[i * 2 + 0] =
        __halves2half2(__float2half_rn(v.x), __float2half_rn(v.y));
    ((__half2*)out16)[i * 2 + 1] =
        __halves2half2(__float2half_rn(v.z), __float2half_rn(v.w));
}

// ---------------------------------------------------------------------------
// transpose + scale + fp16 convert: in [NJ][NI] f32 -> [NI][NJ] fp16
// ---------------------------------------------------------------------------
__global__ void transpose_conv_kernel(const float* __restrict__ in,
                                      __half* __restrict__ out16,
                                      int NJ, int NI, float scale)
{
    __shared__ float t[32][33];
    const int i0 = blockIdx.y * 32;
    const int j0 = blockIdx.x * 32;
    const int x = threadIdx.x, y = threadIdx.y;
#pragma unroll
    for (int r = 0; r < 4; r++)
        t[y + 8 * r][x] = in[(size_t)(j0 + y + 8 * r) * NI + (i0 + x)];
    __syncthreads();
#pragma unroll
    for (int r = 0; r < 4; r++) {
        const int i = i0 + y + 8 * r;
        out16[(size_t)i * NJ + (j0 + x)] =
            __float2half_rn(t[x][y + 8 * r] * scale);
    }
}

// ---------------------------------------------------------------------------
// Kronecker mode contraction (fp32; unchanged from passing kernel)
// ---------------------------------------------------------------------------
__global__ void kron_stage_kernel(const float* __restrict__ in,
                                  float* __restrict__ out,
                                  const float* __restrict__ Q,
                                  int R, int I)
{
    __shared__ float sQ[256];
    __shared__ float sIn[16][256];
    const int tid = threadIdx.x;
    const int o = blockIdx.x * 256 + tid;
    const int a = blockIdx.y / I;
    const int c = blockIdx.y % I;
    if (tid < R * R) sQ[tid] = Q[tid];
    const int rbase = a * R * I + c;
    for (int j = 0; j < R; j++)
        sIn[j][tid] = in[(size_t)(rbase + j * I) * IN_F + o];
    __syncthreads();
    for (int i = 0; i < R; i++) {
        float acc = 0.0f;
        for (int j = 0; j < R; j++)
            acc = fmaf(sQ[i * R + j], sIn[j][tid], acc);
        out[(size_t)(rbase + i * I) * IN_F + o] = acc;
    }
}

// ---------------------------------------------------------------------------
// Warp-MMA 1-term fp16 GEMM: C[m][n] = out_scale * sum_k A[m][k]*B[n][k]
// Block 128x256, K-chunk 64 (128B swizzled rows), 4-stage cp.async pipeline.
// 512 threads: 16 warps (2M x 8N), warp tile 64x32. M,N,K mult of 128/256/64.
// ---------------------------------------------------------------------------
#define GKCH       64
#define SOF_A      0
#define SOF_B      16384                   // A: 128 rows x 128 B
#define STAGE_B    49152                   // + B: 256 rows x 128 B = 48 KB
#define NSTAGE     4
#define GEMM_SMEM  (NSTAGE * STAGE_B + 1024)   // ~193 KB
#define NTHR       512

__device__ __forceinline__ void load_tiles(uint32_t sb,
                                           const char* pA, const char* pB,
                                           size_t ldb, size_t gbase, int tid)
{
    // A tile: 1024 x 16B  (2 per thread)
#pragma unroll
    for (int i = 0; i < 2; i++) {
        int idx = tid + i * NTHR;
        int row = idx >> 3;
        uint32_t c16 = (uint32_t)(idx & 7) << 4;
        uint32_t so = swz128((uint32_t)row * 128u + c16);
        cp16(sb + SOF_A + so, pA + (size_t)row * ldb + gbase + c16);
    }
    // B tile: 2048 x 16B  (4 per thread)
#pragma unroll
    for (int i = 0; i < 4; i++) {
        int idx = tid + i * NTHR;
        int row = idx >> 3;
        uint32_t c16 = (uint32_t)(idx & 7) << 4;
        uint32_t so = swz128((uint32_t)row * 128u + c16);
        cp16(sb + SOF_B + so, pB + (size_t)row * ldb + gbase + c16);
    }
}

__global__ __launch_bounds__(NTHR, 1)
void mma_gemm1(const __half* __restrict__ A,
               const __half* __restrict__ B,
               float* __restrict__ C, int M, int N, int K, float out_scale)
{
    extern __shared__ char dynsmem[];
    const int tid = threadIdx.x;
    const uint32_t smem = (smem_u32(dynsmem) + 1023u) & ~1023u;

    const int w = tid >> 5, lane = tid & 31;
    const int m0 = (w >> 3) * 64;          // 2 M-slabs of 64
    const int n0 = (w & 7) * 32;           // 8 N-slabs of 32

    // ldmatrix lane patterns
    const int rowA  = lane & 15;
    const uint32_t kselA = (uint32_t)(lane >> 4) << 4;       // 0 or 16
    const int rowB  = (lane & 7) + ((lane >> 4) << 3);
    const uint32_t kselB = (uint32_t)((lane >> 3) & 1) << 4; // 0 or 16

    const size_t ldb = (size_t)K * 2;
    const char* pA = (const char*)A + (size_t)blockIdx.y * 128 * ldb;
    const char* pB = (const char*)B + (size_t)blockIdx.x * 256 * ldb;

    // pre-swizzle-input base offsets (swizzle applied after adding kb)
    const uint32_t aOff = (uint32_t)(m0 + rowA) * 128u + kselA;
    const uint32_t bOff = (uint32_t)(n0 + rowB) * 128u + kselB;

    float acc[4][4][4];
#pragma unroll
    for (int a = 0; a < 4; a++)
#pragma unroll
        for (int b = 0; b < 4; b++)
#pragma unroll
            for (int c = 0; c < 4; c++) acc[a][b][c] = 0.0f;

    const int KT = K / GKCH;

    // prologue: stages 0..2
#pragma unroll
    for (int c = 0; c < NSTAGE - 1; c++) {
        load_tiles(smem + c * STAGE_B, pA, pB, ldb, (size_t)c * (GKCH * 2), tid);
        asm volatile("cp.async.commit_group;" ::: "memory");
    }

    for (int kc = 0; kc < KT; kc++) {
        const uint32_t sb = smem + (uint32_t)(kc & (NSTAGE - 1)) * STAGE_B;

        // chunk kc resident (<= NSTAGE-2 groups still in flight)
        asm volatile("cp.async.wait_group %0;" :: "n"(NSTAGE - 2) : "memory");
        __syncthreads();   // all warps done with the buffer retired at kc-1

        // prefetch chunk kc+3 (overlaps with the MMA work below)
        if (kc + NSTAGE - 1 < KT)
            load_tiles(smem + (uint32_t)((kc + NSTAGE - 1) & (NSTAGE - 1)) * STAGE_B,
                       pA, pB, ldb, (size_t)(kc + NSTAGE - 1) * (GKCH * 2), tid);
        asm volatile("cp.async.commit_group;" ::: "memory");

#pragma unroll
        for (int kk = 0; kk < 4; kk++) {
            const uint32_t kb = (uint32_t)kk * 32;
            uint32_t af[4][4], bf[2][4];
#pragma unroll
            for (int mi = 0; mi < 4; mi++)
                ldsm4(af[mi], sb + SOF_A + swz128(aOff + (uint32_t)mi * 2048 + kb));
#pragma unroll
            for (int j = 0; j < 2; j++)
                ldsm4(bf[j], sb + SOF_B + swz128(bOff + (uint32_t)j * 2048 + kb));
#pragma unroll
            for (int mi = 0; mi < 4; mi++)
#pragma unroll
                for (int ni = 0; ni < 4; ni++)
                    mma16816(acc[mi][ni], af[mi], &bf[ni >> 1][(ni & 1) * 2]);
        }
    }

    // epilogue: scale + direct f32 stores
    const int g = lane >> 2, t2 = (lane & 3) * 2;
    const size_t rbase = (size_t)blockIdx.y * 128 + m0;
    const size_t cbase = (size_t)blockIdx.x * 256 + n0;
#pragma unroll
    for (int mi = 0; mi < 4; mi++) {
#pragma unroll
        for (int ni = 0; ni < 4; ni++) {
            float* p0 = C + (rbase + mi * 16 + g) * (size_t)N
                          + cbase + ni * 8 + t2;
            float* p1 = p0 + 8 * (size_t)N;
            *(float2*)p0 = make_float2(acc[mi][ni][0] * out_scale,
                                       acc[mi][ni][1] * out_scale);
            *(float2*)p1 = make_float2(acc[mi][ni][2] * out_scale,
                                       acc[mi][ni][3] * out_scale);
        }
    }
}

// ---------------------------------------------------------------------------
// Launch
// ---------------------------------------------------------------------------
extern "C" void kernel_launch(void* const* d_in, const int* in_sizes, int n_in,
                              void* d_out, int out_size)
{
    (void)in_sizes; (void)n_in; (void)out_size;
    const float* x   = (const float*)d_in[0];
    const float* U   = (const float*)d_in[1];
    const float* S   = (const float*)d_in[2];
    const float* V   = (const float*)d_in[3];
    const float* dlt = (const float*)d_in[4];
    const float* Q1  = (const float*)d_in[5];
    const float* Q2  = (const float*)d_in[6];
    const float* Q3  = (const float*)d_in[7];
    float* out = (float*)d_out;

    __half *xh, *VTh, *Ush, *Wth;
    float *W0, *W1;
    cudaGetSymbolAddress((void**)&xh,  g_xh);
    cudaGetSymbolAddress((void**)&VTh, g_VTh);
    cudaGetSymbolAddress((void**)&Ush, g_Ush);
    cudaGetSymbolAddress((void**)&Wth, g_Wth);
    cudaGetSymbolAddress((void**)&W0,  g_W0);
    cudaGetSymbolAddress((void**)&W1,  g_W1);

    cudaFuncSetAttribute(mma_gemm1,
                         cudaFuncAttributeMaxDynamicSharedMemorySize, GEMM_SMEM);

    // 1) x -> xh (fp16, unscaled)
    {
        size_t n4 = (size_t)SEQ_M * IN_F / 4;
        conv_scale_kernel<<<(unsigned)(n4 / 256), 256>>>(
            x, nullptr, nullptr, xh, n4, IN_F, 1.0f);
    }
    // 2) V [k][d] -> VTh [d][k] (x256)
    transpose_conv_kernel<<<dim3(IN_F / 32, IN_F / 32), dim3(32, 8)>>>(
        V, VTh, IN_F, IN_F, 256.0f);
    // 3) U[o][k]*relu(S[k]+delta[k]) -> Ush (x256)
    {
        size_t n4 = (size_t)IN_F * IN_F / 4;
        conv_scale_kernel<<<(unsigned)(n4 / 256), 256>>>(
            U, S, dlt, Ush, n4, IN_F, 256.0f);
    }
    // 4) W^T[d][o] = (VTh @ Ush^T) / 65536
    mma_gemm1<<<dim3(IN_F / 256, IN_F / 128), NTHR, GEMM_SMEM>>>(
        VTh, Ush, W0, IN_F, IN_F, IN_F, 1.0f / 65536.0f);

    // 5) Kronecker: contract j3 (Q3), j2 (Q2), j1 (Q1); d=(j1*16+j2)*12+j3
    kron_stage_kernel<<<dim3(IN_F / 256, 256), 256>>>(W0, W1, Q3, 12, 1);
    kron_stage_kernel<<<dim3(IN_F / 256, 192), 256>>>(W1, W0, Q2, 16, 12);
    kron_stage_kernel<<<dim3(IN_F / 256, 192), 256>>>(W0, W1, Q1, 16, 192);

    // 6) W_t [d][o] -> Wth [o][d] (x256)
    transpose_conv_kernel<<<dim3(IN_F / 32, IN_F / 32), dim3(32, 8)>>>(
        W1, Wth, IN_F, IN_F, 256.0f);

    // 7) out[m][o] = (xh @ Wth^T) / 256
    mma_gemm1<<<dim3(IN_F / 256, SEQ_M / 128), NTHR, GEMM_SMEM>>>(
        xh, Wth, out, SEQ_M, IN_F, IN_F, 1.0f / 256.0f);
}

// round 13
// speedup vs baseline: 10.5726x; 1.0835x over previous
#include <cuda_runtime.h>
#include <cuda_fp16.h>
#include <cstdint>
#include <cstddef>

// ---------------------------------------------------------------------------
// InjectedSODA_SVD: out = x @ ( (Q1⊗Q2⊗Q3) @ ((U*relu(S+delta)) @ V)^T )
//
// Pure fp16 1-term warp-MMA (m16n8k16 f16->f32), rel_err 4.15e-4 (measured).
// Weight-path operands pre-scaled x256 (exact power of two) to avoid fp16
// subnormals in W_t; epilogues divide it back out.
//
// R13 = R12 with the deadlock fix: cp.async.mbarrier.arrive must be the
// .noinc form. The default form increments the pending count before arming
// the async arrival (net zero against the init count), so full[s] never
// completed a phase and every consumer spun forever (the R12 120s timeout).
//
// GEMM mainloop: mbarrier producer/consumer ring (sm_80-era PTX only):
//   full[s]  count=512, armed via cp.async.mbarrier.arrive.noinc per thread
//   empty[s] count=16,  lane-0 per warp after consuming the stage
// No bar.sync in the loop; warp skew bounded at 3 chunks by the ring.
// ---------------------------------------------------------------------------

#define IN_F   3072
#define SEQ_M  16384

// ---------------- scratch (device globals; allocation is forbidden) --------
__device__ __align__(1024) __half g_xh [(size_t)SEQ_M * IN_F];
__device__ __align__(1024) __half g_VTh[(size_t)IN_F * IN_F];
__device__ __align__(1024) __half g_Ush[(size_t)IN_F * IN_F];
__device__ __align__(1024) __half g_Wth[(size_t)IN_F * IN_F];
__device__ __align__(1024) float  g_W0[(size_t)IN_F * IN_F];
__device__ __align__(1024) float  g_W1[(size_t)IN_F * IN_F];

// ---------------- PTX helpers (base-target, sm_80-era only) -----------------
__device__ __forceinline__ uint32_t smem_u32(const void* p) {
    uint32_t a;
    asm("{ .reg .u64 t; cvta.to.shared.u64 t, %1; cvt.u32.u64 %0, t; }"
        : "=r"(a) : "l"(p));
    return a;
}
__device__ __forceinline__ uint32_t swz128(uint32_t o) {
    return o ^ ((o >> 3) & 0x70);
}
__device__ __forceinline__ void cp16(uint32_t dst, const void* src) {
    asm volatile("cp.async.cg.shared.global [%0], [%1], 16;"
                 :: "r"(dst), "l"(src));
}
__device__ __forceinline__ void ldsm4(uint32_t* r, uint32_t addr) {
    asm volatile("ldmatrix.sync.aligned.m8n8.x4.shared.b16 {%0,%1,%2,%3}, [%4];"
                 : "=r"(r[0]), "=r"(r[1]), "=r"(r[2]), "=r"(r[3])
                 : "r"(addr));
}
__device__ __forceinline__ void mma16816(float* c, const uint32_t* a,
                                         const uint32_t* b) {
    asm volatile(
        "mma.sync.aligned.m16n8k16.row.col.f32.f16.f16.f32 "
        "{%0,%1,%2,%3}, {%4,%5,%6,%7}, {%8,%9}, {%0,%1,%2,%3};"
        : "+f"(c[0]), "+f"(c[1]), "+f"(c[2]), "+f"(c[3])
        : "r"(a[0]), "r"(a[1]), "r"(a[2]), "r"(a[3]), "r"(b[0]), "r"(b[1]));
}
__device__ __forceinline__ void mbar_init(uint32_t a, uint32_t n) {
    asm volatile("mbarrier.init.shared.b64 [%0], %1;"
                 :: "r"(a), "r"(n) : "memory");
}
__device__ __forceinline__ void mbar_arrive(uint32_t a) {
    asm volatile("{\n\t.reg .b64 t;\n\tmbarrier.arrive.shared.b64 t, [%0];\n\t}"
                 :: "r"(a) : "memory");
}
__device__ __forceinline__ void cpasync_mbar_arrive(uint32_t a) {
    // .noinc: consume one of the pre-initialized arrival counts. The default
    // form increments pending first (net zero) and the phase never completes.
    asm volatile("cp.async.mbarrier.arrive.noinc.shared.b64 [%0];"
                 :: "r"(a) : "memory");
}
__device__ __forceinline__ void mbar_wait(uint32_t a, uint32_t parity) {
    uint32_t done;
    asm volatile(
        "{\n\t.reg .pred P;\n\t"
        "mbarrier.test_wait.parity.shared.b64 P, [%1], %2;\n\t"
        "selp.b32 %0, 1, 0, P;\n\t}"
        : "=r"(done) : "r"(a), "r"(parity) : "memory");
    while (!done) {
        asm volatile("nanosleep.u32 32;");
        asm volatile(
            "{\n\t.reg .pred P;\n\t"
            "mbarrier.test_wait.parity.shared.b64 P, [%1], %2;\n\t"
            "selp.b32 %0, 1, 0, P;\n\t}"
            : "=r"(done) : "r"(a), "r"(parity) : "memory");
    }
}

// ---------------------------------------------------------------------------
// scale(+optional per-col relu(S+D)) then fp16 convert
// ---------------------------------------------------------------------------
__global__ void conv_scale_kernel(const float* __restrict__ in,
                                  const float* __restrict__ S,
                                  const float* __restrict__ D,
                                  __half* __restrict__ out16,
                                  size_t n4, int cols, float scale)
{
    size_t i = (size_t)blockIdx.x * blockDim.x + threadIdx.x;
    if (i >= n4) return;
    float4 v = ((const float4*)in)[i];
    if (S) {
        int c = (int)((i * 4) % (size_t)cols);
        v.x *= fmaxf(S[c + 0] + D[c + 0], 0.0f);
        v.y *= fmaxf(S[c + 1] + D[c + 1], 0.0f);
        v.z *= fmaxf(S[c + 2] + D[c + 2], 0.0f);
        v.w *= fmaxf(S[c + 3] + D[c + 3], 0.0f);
    }
    v.x *= scale; v.y *= scale; v.z *= scale; v.w *= scale;
    ((__half2*)out16)[i * 2 + 0] =
        __halves2half2(__float2half_rn(v.x), __float2half_rn(v.y));
    ((__half2*)out16)[i * 2 + 1] =
        __halves2half2(__float2half_rn(v.z), __float2half_rn(v.w));
}

// ---------------------------------------------------------------------------
// transpose + scale + fp16 convert: in [NJ][NI] f32 -> [NI][NJ] fp16
// ---------------------------------------------------------------------------
__global__ void transpose_conv_kernel(const float* __restrict__ in,
                                      __half* __restrict__ out16,
                                      int NJ, int NI, float scale)
{
    __shared__ float t[32][33];
    const int i0 = blockIdx.y * 32;
    const int j0 = blockIdx.x * 32;
    const int x = threadIdx.x, y = threadIdx.y;
#pragma unroll
    for (int r = 0; r < 4; r++)
        t[y + 8 * r][x] = in[(size_t)(j0 + y + 8 * r) * NI + (i0 + x)];
    __syncthreads();
#pragma unroll
    for (int r = 0; r < 4; r++) {
        const int i = i0 + y + 8 * r;
        out16[(size_t)i * NJ + (j0 + x)] =
            __float2half_rn(t[x][y + 8 * r] * scale);
    }
}

// ---------------------------------------------------------------------------
// Kronecker mode contraction (fp32; unchanged from passing kernel)
// ---------------------------------------------------------------------------
__global__ void kron_stage_kernel(const float* __restrict__ in,
                                  float* __restrict__ out,
                                  const float* __restrict__ Q,
                                  int R, int I)
{
    __shared__ float sQ[256];
    __shared__ float sIn[16][256];
    const int tid = threadIdx.x;
    const int o = blockIdx.x * 256 + tid;
    const int a = blockIdx.y / I;
    const int c = blockIdx.y % I;
    if (tid < R * R) sQ[tid] = Q[tid];
    const int rbase = a * R * I + c;
    for (int j = 0; j < R; j++)
        sIn[j][tid] = in[(size_t)(rbase + j * I) * IN_F + o];
    __syncthreads();
    for (int i = 0; i < R; i++) {
        float acc = 0.0f;
        for (int j = 0; j < R; j++)
            acc = fmaf(sQ[i * R + j], sIn[j][tid], acc);
        out[(size_t)(rbase + i * I) * IN_F + o] = acc;
    }
}

// ---------------------------------------------------------------------------
// Warp-MMA 1-term fp16 GEMM: C[m][n] = out_scale * sum_k A[m][k]*B[n][k]
// Block 128x256, K-chunk 64 (128B swizzled rows), 4-stage mbarrier pipeline.
// 512 threads: 16 warps (2M x 8N), warp tile 64x32. M,N,K mult of 128/256/64.
// ---------------------------------------------------------------------------
#define GKCH       64
#define SOF_A      0
#define SOF_B      16384                   // A: 128 rows x 128 B
#define STAGE_B    49152                   // + B: 256 rows x 128 B = 48 KB
#define NSTAGE     4
#define GEMM_SMEM  (NSTAGE * STAGE_B + 1024)   // ~193 KB
#define NTHR       512

__device__ __forceinline__ void load_tiles(uint32_t sb,
                                           const char* pA, const char* pB,
                                           size_t ldb, size_t gbase, int tid)
{
    // A tile: 1024 x 16B  (2 per thread)
#pragma unroll
    for (int i = 0; i < 2; i++) {
        int idx = tid + i * NTHR;
        int row = idx >> 3;
        uint32_t c16 = (uint32_t)(idx & 7) << 4;
        uint32_t so = swz128((uint32_t)row * 128u + c16);
        cp16(sb + SOF_A + so, pA + (size_t)row * ldb + gbase + c16);
    }
    // B tile: 2048 x 16B  (4 per thread)
#pragma unroll
    for (int i = 0; i < 4; i++) {
        int idx = tid + i * NTHR;
        int row = idx >> 3;
        uint32_t c16 = (uint32_t)(idx & 7) << 4;
        uint32_t so = swz128((uint32_t)row * 128u + c16);
        cp16(sb + SOF_B + so, pB + (size_t)row * ldb + gbase + c16);
    }
}

__global__ __launch_bounds__(NTHR, 1)
void mma_gemm1(const __half* __restrict__ A,
               const __half* __restrict__ B,
               float* __restrict__ C, int M, int N, int K, float out_scale)
{
    extern __shared__ char dynsmem[];
    __shared__ __align__(8) unsigned long long s_bar[2 * NSTAGE];

    const int tid = threadIdx.x;
    const uint32_t smem = (smem_u32(dynsmem) + 1023u) & ~1023u;
    const uint32_t barb = smem_u32(s_bar);   // full[s]=barb+8s, empty[s]=barb+32+8s

    const int w = tid >> 5, lane = tid & 31;
    const int m0 = (w >> 3) * 64;          // 2 M-slabs of 64
    const int n0 = (w & 7) * 32;           // 8 N-slabs of 32

    // ldmatrix lane patterns
    const int rowA  = lane & 15;
    const uint32_t kselA = (uint32_t)(lane >> 4) << 4;       // 0 or 16
    const int rowB  = (lane & 7) + ((lane >> 4) << 3);
    const uint32_t kselB = (uint32_t)((lane >> 3) & 1) << 4; // 0 or 16

    const size_t ldb = (size_t)K * 2;
    const char* pA = (const char*)A + (size_t)blockIdx.y * 128 * ldb;
    const char* pB = (const char*)B + (size_t)blockIdx.x * 256 * ldb;

    const uint32_t aOff = (uint32_t)(m0 + rowA) * 128u + kselA;
    const uint32_t bOff = (uint32_t)(n0 + rowB) * 128u + kselB;

    // barrier init: full count=NTHR (cp.async arrivals), empty count=16 warps
    if (tid == 0) {
#pragma unroll
        for (int s = 0; s < NSTAGE; s++) {
            mbar_init(barb + 8u * s, NTHR);
            mbar_init(barb + 32u + 8u * s, 16);
        }
    }
    __syncthreads();

    float acc[4][4][4];
#pragma unroll
    for (int a = 0; a < 4; a++)
#pragma unroll
        for (int b = 0; b < 4; b++)
#pragma unroll
            for (int c = 0; c < 4; c++) acc[a][b][c] = 0.0f;

    const int KT = K / GKCH;

    // prologue: chunks 0..2 -> stages 0..2 (no empty wait: first use)
#pragma unroll
    for (int c = 0; c < NSTAGE - 1; c++) {
        load_tiles(smem + c * STAGE_B, pA, pB, ldb, (size_t)c * (GKCH * 2), tid);
        cpasync_mbar_arrive(barb + 8u * c);
    }

    for (int kc = 0; kc < KT; kc++) {
        const uint32_t s  = (uint32_t)kc & (NSTAGE - 1);
        const uint32_t sb = smem + s * STAGE_B;

        // consumer: wait chunk kc's data
        mbar_wait(barb + 8u * s, (uint32_t)(kc >> 2) & 1u);

#pragma unroll
        for (int kk = 0; kk < 4; kk++) {
            const uint32_t kb = (uint32_t)kk * 32;
            uint32_t af[4][4], bf[2][4];
#pragma unroll
            for (int mi = 0; mi < 4; mi++)
                ldsm4(af[mi], sb + SOF_A + swz128(aOff + (uint32_t)mi * 2048 + kb));
#pragma unroll
            for (int j = 0; j < 2; j++)
                ldsm4(bf[j], sb + SOF_B + swz128(bOff + (uint32_t)j * 2048 + kb));
#pragma unroll
            for (int mi = 0; mi < 4; mi++)
#pragma unroll
                for (int ni = 0; ni < 4; ni++)
                    mma16816(acc[mi][ni], af[mi], &bf[ni >> 1][(ni & 1) * 2]);
        }

        // this warp is done reading stage s
        __syncwarp();
        if (lane == 0) mbar_arrive(barb + 32u + 8u * s);

        // producer (off critical path): issue loads for chunk kc+3
        const int kn = kc + NSTAGE - 1;
        if (kn < KT) {
            const uint32_t sn = (uint32_t)kn & (NSTAGE - 1);
            if (kn >= NSTAGE)   // stage previously held chunk kn-4
                mbar_wait(barb + 32u + 8u * sn,
                          (uint32_t)((kn - NSTAGE) >> 2) & 1u);
            load_tiles(smem + sn * STAGE_B, pA, pB, ldb,
                       (size_t)kn * (GKCH * 2), tid);
            cpasync_mbar_arrive(barb + 8u * sn);
        }
    }

    // epilogue: scale + direct f32 stores
    const int g = lane >> 2, t2 = (lane & 3) * 2;
    const size_t rbase = (size_t)blockIdx.y * 128 + m0;
    const size_t cbase = (size_t)blockIdx.x * 256 + n0;
#pragma unroll
    for (int mi = 0; mi < 4; mi++) {
#pragma unroll
        for (int ni = 0; ni < 4; ni++) {
            float* p0 = C + (rbase + mi * 16 + g) * (size_t)N
                          + cbase + ni * 8 + t2;
            float* p1 = p0 + 8 * (size_t)N;
            *(float2*)p0 = make_float2(acc[mi][ni][0] * out_scale,
                                       acc[mi][ni][1] * out_scale);
            *(float2*)p1 = make_float2(acc[mi][ni][2] * out_scale,
                                       acc[mi][ni][3] * out_scale);
        }
    }
}

// ---------------------------------------------------------------------------
// Launch
// ---------------------------------------------------------------------------
extern "C" void kernel_launch(void* const* d_in, const int* in_sizes, int n_in,
                              void* d_out, int out_size)
{
    (void)in_sizes; (void)n_in; (void)out_size;
    const float* x   = (const float*)d_in[0];
    const float* U   = (const float*)d_in[1];
    const float* S   = (const float*)d_in[2];
    const float* V   = (const float*)d_in[3];
    const float* dlt = (const float*)d_in[4];
    const float* Q1  = (const float*)d_in[5];
    const float* Q2  = (const float*)d_in[6];
    const float* Q3  = (const float*)d_in[7];
    float* out = (float*)d_out;

    __half *xh, *VTh, *Ush, *Wth;
    float *W0, *W1;
    cudaGetSymbolAddress((void**)&xh,  g_xh);
    cudaGetSymbolAddress((void**)&VTh, g_VTh);
    cudaGetSymbolAddress((void**)&Ush, g_Ush);
    cudaGetSymbolAddress((void**)&Wth, g_Wth);
    cudaGetSymbolAddress((void**)&W0,  g_W0);
    cudaGetSymbolAddress((void**)&W1,  g_W1);

    cudaFuncSetAttribute(mma_gemm1,
                         cudaFuncAttributeMaxDynamicSharedMemorySize, GEMM_SMEM);

    // 1) x -> xh (fp16, unscaled)
    {
        size_t n4 = (size_t)SEQ_M * IN_F / 4;
        conv_scale_kernel<<<(unsigned)(n4 / 256), 256>>>(
            x, nullptr, nullptr, xh, n4, IN_F, 1.0f);
    }
    // 2) V [k][d] -> VTh [d][k] (x256)
    transpose_conv_kernel<<<dim3(IN_F / 32, IN_F / 32), dim3(32, 8)>>>(
        V, VTh, IN_F, IN_F, 256.0f);
    // 3) U[o][k]*relu(S[k]+delta[k]) -> Ush (x256)
    {
        size_t n4 = (size_t)IN_F * IN_F / 4;
        conv_scale_kernel<<<(unsigned)(n4 / 256), 256>>>(
            U, S, dlt, Ush, n4, IN_F, 256.0f);
    }
    // 4) W^T[d][o] = (VTh @ Ush^T) / 65536
    mma_gemm1<<<dim3(IN_F / 256, IN_F / 128), NTHR, GEMM_SMEM>>>(
        VTh, Ush, W0, IN_F, IN_F, IN_F, 1.0f / 65536.0f);

    // 5) Kronecker: contract j3 (Q3), j2 (Q2), j1 (Q1); d=(j1*16+j2)*12+j3
    kron_stage_kernel<<<dim3(IN_F / 256, 256), 256>>>(W0, W1, Q3, 12, 1);
    kron_stage_kernel<<<dim3(IN_F / 256, 192), 256>>>(W1, W0, Q2, 16, 12);
    kron_stage_kernel<<<dim3(IN_F / 256, 192), 256>>>(W0, W1, Q1, 16, 192);

    // 6) W_t [d][o] -> Wth [o][d] (x256)
    transpose_conv_kernel<<<dim3(IN_F / 32, IN_F / 32), dim3(32, 8)>>>(
        W1, Wth, IN_F, IN_F, 256.0f);

    // 7) out[m][o] = (xh @ Wth^T) / 256
    mma_gemm1<<<dim3(IN_F / 256, SEQ_M / 128), NTHR, GEMM_SMEM>>>(
        xh, Wth, out, SEQ_M, IN_F, IN_F, 1.0f / 256.0f);
}

// round 14
// speedup vs baseline: 11.2333x; 1.0625x over previous
#include <cuda_runtime.h>
#include <cuda_fp16.h>
#include <cstdint>
#include <cstddef>

// ---------------------------------------------------------------------------
// InjectedSODA_SVD: out = x @ ( (Q1⊗Q2⊗Q3) @ ((U*relu(S+delta)) @ V)^T )
//
// Pure fp16 1-term warp-MMA (m16n8k16 f16->f32), rel_err 4.15e-4 (measured).
// Weight-path operands pre-scaled x256 (exact power of two) to avoid fp16
// subnormals in W_t; epilogues divide it back out.
//
// R14 changes vs R13 (1002us, tensor 74.2%, L1 61.6% = smem-port co-bound):
//  1. GEMM: 8 warps / 256 threads, warp tile 64x64 (was 16 warps / 64x32).
//     LDSM bytes/MAC drop 0.094 -> 0.061; per-chunk smem traffic 144KB->112KB,
//     un-binding the smem port. Same mbarrier free-running ring as R13
//     (full[s] count=256 via cp.async.mbarrier.arrive.noinc, empty[s] count=8).
//  2. Kron stages Q3+Q2 fused into one smem-resident kernel (two in-smem
//     passes, same per-element FLOP order -> bitwise identical), saving one
//     full 150MB global round-trip.
// ---------------------------------------------------------------------------

#define IN_F   3072
#define SEQ_M  16384

// ---------------- scratch (device globals; allocation is forbidden) --------
__device__ __align__(1024) __half g_xh [(size_t)SEQ_M * IN_F];
__device__ __align__(1024) __half g_VTh[(size_t)IN_F * IN_F];
__device__ __align__(1024) __half g_Ush[(size_t)IN_F * IN_F];
__device__ __align__(1024) __half g_Wth[(size_t)IN_F * IN_F];
__device__ __align__(1024) float  g_W0[(size_t)IN_F * IN_F];
__device__ __align__(1024) float  g_W1[(size_t)IN_F * IN_F];

// ---------------- PTX helpers (base-target, sm_80-era only) -----------------
__device__ __forceinline__ uint32_t smem_u32(const void* p) {
    uint32_t a;
    asm("{ .reg .u64 t; cvta.to.shared.u64 t, %1; cvt.u32.u64 %0, t; }"
        : "=r"(a) : "l"(p));
    return a;
}
__device__ __forceinline__ uint32_t swz128(uint32_t o) {
    return o ^ ((o >> 3) & 0x70);
}
__device__ __forceinline__ void cp16(uint32_t dst, const void* src) {
    asm volatile("cp.async.cg.shared.global [%0], [%1], 16;"
                 :: "r"(dst), "l"(src));
}
__device__ __forceinline__ void ldsm4(uint32_t* r, uint32_t addr) {
    asm volatile("ldmatrix.sync.aligned.m8n8.x4.shared.b16 {%0,%1,%2,%3}, [%4];"
                 : "=r"(r[0]), "=r"(r[1]), "=r"(r[2]), "=r"(r[3])
                 : "r"(addr));
}
__device__ __forceinline__ void mma16816(float* c, const uint32_t* a,
                                         const uint32_t* b) {
    asm volatile(
        "mma.sync.aligned.m16n8k16.row.col.f32.f16.f16.f32 "
        "{%0,%1,%2,%3}, {%4,%5,%6,%7}, {%8,%9}, {%0,%1,%2,%3};"
        : "+f"(c[0]), "+f"(c[1]), "+f"(c[2]), "+f"(c[3])
        : "r"(a[0]), "r"(a[1]), "r"(a[2]), "r"(a[3]), "r"(b[0]), "r"(b[1]));
}
__device__ __forceinline__ void mbar_init(uint32_t a, uint32_t n) {
    asm volatile("mbarrier.init.shared.b64 [%0], %1;"
                 :: "r"(a), "r"(n) : "memory");
}
__device__ __forceinline__ void mbar_arrive(uint32_t a) {
    asm volatile("{\n\t.reg .b64 t;\n\tmbarrier.arrive.shared.b64 t, [%0];\n\t}"
                 :: "r"(a) : "memory");
}
__device__ __forceinline__ void cpasync_mbar_arrive(uint32_t a) {
    // .noinc: consume one pre-initialized arrival (default form deadlocks).
    asm volatile("cp.async.mbarrier.arrive.noinc.shared.b64 [%0];"
                 :: "r"(a) : "memory");
}
__device__ __forceinline__ void mbar_wait(uint32_t a, uint32_t parity) {
    uint32_t done;
    asm volatile(
        "{\n\t.reg .pred P;\n\t"
        "mbarrier.test_wait.parity.shared.b64 P, [%1], %2;\n\t"
        "selp.b32 %0, 1, 0, P;\n\t}"
        : "=r"(done) : "r"(a), "r"(parity) : "memory");
    while (!done) {
        asm volatile("nanosleep.u32 32;");
        asm volatile(
            "{\n\t.reg .pred P;\n\t"
            "mbarrier.test_wait.parity.shared.b64 P, [%1], %2;\n\t"
            "selp.b32 %0, 1, 0, P;\n\t}"
            : "=r"(done) : "r"(a), "r"(parity) : "memory");
    }
}

// ---------------------------------------------------------------------------
// scale(+optional per-col relu(S+D)) then fp16 convert
// ---------------------------------------------------------------------------
__global__ void conv_scale_kernel(const float* __restrict__ in,
                                  const float* __restrict__ S,
                                  const float* __restrict__ D,
                                  __half* __restrict__ out16,
                                  size_t n4, int cols, float scale)
{
    size_t i = (size_t)blockIdx.x * blockDim.x + threadIdx.x;
    if (i >= n4) return;
    float4 v = ((const float4*)in)[i];
    if (S) {
        int c = (int)((i * 4) % (size_t)cols);
        v.x *= fmaxf(S[c + 0] + D[c + 0], 0.0f);
        v.y *= fmaxf(S[c + 1] + D[c + 1], 0.0f);
        v.z *= fmaxf(S[c + 2] + D[c + 2], 0.0f);
        v.w *= fmaxf(S[c + 3] + D[c + 3], 0.0f);
    }
    v.x *= scale; v.y *= scale; v.z *= scale; v.w *= scale;
    ((__half2*)out16)[i * 2 + 0] =
        __halves2half2(__float2half_rn(v.x), __float2half_rn(v.y));
    ((__half2*)out16)[i * 2 + 1] =
        __halves2half2(__float2half_rn(v.z), __float2half_rn(v.w));
}

// ---------------------------------------------------------------------------
// transpose + scale + fp16 convert: in [NJ][NI] f32 -> [NI][NJ] fp16
// ---------------------------------------------------------------------------
__global__ void transpose_conv_kernel(const float* __restrict__ in,
                                      __half* __restrict__ out16,
                                      int NJ, int NI, float scale)
{
    __shared__ float t[32][33];
    const int i0 = blockIdx.y * 32;
    const int j0 = blockIdx.x * 32;
    const int x = threadIdx.x, y = threadIdx.y;
#pragma unroll
    for (int r = 0; r < 4; r++)
        t[y + 8 * r][x] = in[(size_t)(j0 + y + 8 * r) * NI + (i0 + x)];
    __syncthreads();
#pragma unroll
    for (int r = 0; r < 4; r++) {
        const int i = i0 + y + 8 * r;
        out16[(size_t)i * NJ + (j0 + x)] =
            __float2half_rn(t[x][y + 8 * r] * scale);
    }
}

// ---------------------------------------------------------------------------
// Fused Kronecker Q3+Q2 stages, smem-resident (bitwise identical to the two
// staged passes). d = (j1*16 + j2)*12 + j3; block: j1 = blockIdx.y (0..15),
// o-tile = 64 cols. Pass1 applies Q3 within each 12-row group; pass2 applies
// Q2 across the 16 groups. Each (row-group, col) cell is owned by exactly
// one thread within a pass -> in-place smem update is race-free.
// ---------------------------------------------------------------------------
__global__ void kron23_kernel(const float* __restrict__ in,
                              float* __restrict__ out,
                              const float* __restrict__ Q2,
                              const float* __restrict__ Q3)
{
    extern __shared__ float t[];              // [192][64] = 48 KB
    __shared__ float sQ2[256], sQ3[144];
    const int tid = threadIdx.x;              // 256
    const int oc = tid & 63, g = tid >> 6;    // col 0..63, group 0..3
    if (tid < 144) sQ3[tid] = Q3[tid];
    sQ2[tid] = Q2[tid];
    const size_t base = (size_t)blockIdx.y * 192 * IN_F + blockIdx.x * 64;

    for (int r = g; r < 192; r += 4)
        t[r * 64 + oc] = in[base + (size_t)r * IN_F + oc];
    __syncthreads();

    // pass 1 (Q3): groups c2 = j2; thread owns c2 in {g, g+4, g+8, g+12}
    for (int c2 = g; c2 < 16; c2 += 4) {
        float v[12], o[12];
#pragma unroll
        for (int j = 0; j < 12; j++) v[j] = t[(c2 * 12 + j) * 64 + oc];
#pragma unroll
        for (int i = 0; i < 12; i++) {
            float acc = 0.0f;
#pragma unroll
            for (int j = 0; j < 12; j++)
                acc = fmaf(sQ3[i * 12 + j], v[j], acc);
            o[i] = acc;
        }
#pragma unroll
        for (int i = 0; i < 12; i++) t[(c2 * 12 + i) * 64 + oc] = o[i];
    }
    __syncthreads();

    // pass 2 (Q2): rows j2*12 + i3; thread owns i3 in {3g .. 3g+2}
    for (int i3 = g * 3; i3 < g * 3 + 3; i3++) {
        float v[16];
#pragma unroll
        for (int j = 0; j < 16; j++) v[j] = t[(j * 12 + i3) * 64 + oc];
#pragma unroll
        for (int i2 = 0; i2 < 16; i2++) {
            float acc = 0.0f;
#pragma unroll
            for (int j = 0; j < 16; j++)
                acc = fmaf(sQ2[i2 * 16 + j], v[j], acc);
            out[base + (size_t)(i2 * 12 + i3) * IN_F + oc] = acc;
        }
    }
}

// ---------------------------------------------------------------------------
// Kronecker mode contraction (fp32) — used for the Q1 stage (R=16, I=192)
// ---------------------------------------------------------------------------
__global__ void kron_stage_kernel(const float* __restrict__ in,
                                  float* __restrict__ out,
                                  const float* __restrict__ Q,
                                  int R, int I)
{
    __shared__ float sQ[256];
    __shared__ float sIn[16][256];
    const int tid = threadIdx.x;
    const int o = blockIdx.x * 256 + tid;
    const int a = blockIdx.y / I;
    const int c = blockIdx.y % I;
    if (tid < R * R) sQ[tid] = Q[tid];
    const int rbase = a * R * I + c;
    for (int j = 0; j < R; j++)
        sIn[j][tid] = in[(size_t)(rbase + j * I) * IN_F + o];
    __syncthreads();
    for (int i = 0; i < R; i++) {
        float acc = 0.0f;
        for (int j = 0; j < R; j++)
            acc = fmaf(sQ[i * R + j], sIn[j][tid], acc);
        out[(size_t)(rbase + i * I) * IN_F + o] = acc;
    }
}

// ---------------------------------------------------------------------------
// Warp-MMA 1-term fp16 GEMM: C[m][n] = out_scale * sum_k A[m][k]*B[n][k]
// Block 128x256, K-chunk 64 (128B swizzled rows), 4-stage mbarrier pipeline.
// 256 threads: 8 warps (2M x 4N), warp tile 64x64. M,N,K mult of 128/256/64.
// ---------------------------------------------------------------------------
#define GKCH       64
#define SOF_A      0
#define SOF_B      16384                   // A: 128 rows x 128 B
#define STAGE_B    49152                   // + B: 256 rows x 128 B = 48 KB
#define NSTAGE     4
#define GEMM_SMEM  (NSTAGE * STAGE_B + 1024)   // ~193 KB
#define NTHR       256

__device__ __forceinline__ void load_tiles(uint32_t sb,
                                           const char* pA, const char* pB,
                                           size_t ldb, size_t gbase, int tid)
{
    // A tile: 1024 x 16B  (4 per thread)
#pragma unroll
    for (int i = 0; i < 4; i++) {
        int idx = tid + i * NTHR;
        int row = idx >> 3;
        uint32_t c16 = (uint32_t)(idx & 7) << 4;
        uint32_t so = swz128((uint32_t)row * 128u + c16);
        cp16(sb + SOF_A + so, pA + (size_t)row * ldb + gbase + c16);
    }
    // B tile: 2048 x 16B  (8 per thread)
#pragma unroll
    for (int i = 0; i < 8; i++) {
        int idx = tid + i * NTHR;
        int row = idx >> 3;
        uint32_t c16 = (uint32_t)(idx & 7) << 4;
        uint32_t so = swz128((uint32_t)row * 128u + c16);
        cp16(sb + SOF_B + so, pB + (size_t)row * ldb + gbase + c16);
    }
}

__global__ __launch_bounds__(NTHR, 1)
void mma_gemm1(const __half* __restrict__ A,
               const __half* __restrict__ B,
               float* __restrict__ C, int M, int N, int K, float out_scale)
{
    extern __shared__ char dynsmem[];
    __shared__ __align__(8) unsigned long long s_bar[2 * NSTAGE];

    const int tid = threadIdx.x;
    const uint32_t smem = (smem_u32(dynsmem) + 1023u) & ~1023u;
    const uint32_t barb = smem_u32(s_bar);   // full[s]=barb+8s, empty[s]=barb+32+8s

    const int w = tid >> 5, lane = tid & 31;
    const int m0 = (w >> 2) * 64;          // 2 M-slabs of 64
    const int n0 = (w & 3) * 64;           // 4 N-slabs of 64

    // ldmatrix lane patterns
    const int rowA  = lane & 15;
    const uint32_t kselA = (uint32_t)(lane >> 4) << 4;       // 0 or 16
    const int rowB  = (lane & 7) + ((lane >> 4) << 3);
    const uint32_t kselB = (uint32_t)((lane >> 3) & 1) << 4; // 0 or 16

    const size_t ldb = (size_t)K * 2;
    const char* pA = (const char*)A + (size_t)blockIdx.y * 128 * ldb;
    const char* pB = (const char*)B + (size_t)blockIdx.x * 256 * ldb;

    const uint32_t aOff = (uint32_t)(m0 + rowA) * 128u + kselA;
    const uint32_t bOff = (uint32_t)(n0 + rowB) * 128u + kselB;

    // barrier init: full count=NTHR (cp.async arrivals), empty count=8 warps
    if (tid == 0) {
#pragma unroll
        for (int s = 0; s < NSTAGE; s++) {
            mbar_init(barb + 8u * s, NTHR);
            mbar_init(barb + 32u + 8u * s, 8);
        }
    }
    __syncthreads();

    float acc[4][8][4];
#pragma unroll
    for (int a = 0; a < 4; a++)
#pragma unroll
        for (int b = 0; b < 8; b++)
#pragma unroll
            for (int c = 0; c < 4; c++) acc[a][b][c] = 0.0f;

    const int KT = K / GKCH;

    // prologue: chunks 0..2 -> stages 0..2 (no empty wait: first use)
#pragma unroll
    for (int c = 0; c < NSTAGE - 1; c++) {
        load_tiles(smem + c * STAGE_B, pA, pB, ldb, (size_t)c * (GKCH * 2), tid);
        cpasync_mbar_arrive(barb + 8u * c);
    }

    for (int kc = 0; kc < KT; kc++) {
        const uint32_t s  = (uint32_t)kc & (NSTAGE - 1);
        const uint32_t sb = smem + s * STAGE_B;

        // consumer: wait chunk kc's data
        mbar_wait(barb + 8u * s, (uint32_t)(kc >> 2) & 1u);

#pragma unroll
        for (int kk = 0; kk < 4; kk++) {
            const uint32_t kb = (uint32_t)kk * 32;
            uint32_t af[4][4], bf[4][4];
#pragma unroll
            for (int mi = 0; mi < 4; mi++)
                ldsm4(af[mi], sb + SOF_A + swz128(aOff + (uint32_t)mi * 2048 + kb));
#pragma unroll
            for (int j = 0; j < 4; j++)
                ldsm4(bf[j], sb + SOF_B + swz128(bOff + (uint32_t)j * 2048 + kb));
#pragma unroll
            for (int mi = 0; mi < 4; mi++)
#pragma unroll
                for (int ni = 0; ni < 8; ni++)
                    mma16816(acc[mi][ni], af[mi], &bf[ni >> 1][(ni & 1) * 2]);
        }

        // this warp is done reading stage s
        __syncwarp();
        if (lane == 0) mbar_arrive(barb + 32u + 8u * s);

        // producer (off critical path): issue loads for chunk kc+3
        const int kn = kc + NSTAGE - 1;
        if (kn < KT) {
            const uint32_t sn = (uint32_t)kn & (NSTAGE - 1);
            if (kn >= NSTAGE)   // stage previously held chunk kn-4
                mbar_wait(barb + 32u + 8u * sn,
                          (uint32_t)((kn - NSTAGE) >> 2) & 1u);
            load_tiles(smem + sn * STAGE_B, pA, pB, ldb,
                       (size_t)kn * (GKCH * 2), tid);
            cpasync_mbar_arrive(barb + 8u * sn);
        }
    }

    // epilogue: scale + direct f32 stores
    const int g = lane >> 2, t2 = (lane & 3) * 2;
    const size_t rbase = (size_t)blockIdx.y * 128 + m0;
    const size_t cbase = (size_t)blockIdx.x * 256 + n0;
#pragma unroll
    for (int mi = 0; mi < 4; mi++) {
#pragma unroll
        for (int ni = 0; ni < 8; ni++) {
            float* p0 = C + (rbase + mi * 16 + g) * (size_t)N
                          + cbase + ni * 8 + t2;
            float* p1 = p0 + 8 * (size_t)N;
            *(float2*)p0 = make_float2(acc[mi][ni][0] * out_scale,
                                       acc[mi][ni][1] * out_scale);
            *(float2*)p1 = make_float2(acc[mi][ni][2] * out_scale,
                                       acc[mi][ni][3] * out_scale);
        }
    }
}

// ---------------------------------------------------------------------------
// Launch
// ---------------------------------------------------------------------------
extern "C" void kernel_launch(void* const* d_in, const int* in_sizes, int n_in,
                              void* d_out, int out_size)
{
    (void)in_sizes; (void)n_in; (void)out_size;
    const float* x   = (const float*)d_in[0];
    const float* U   = (const float*)d_in[1];
    const float* S   = (const float*)d_in[2];
    const float* V   = (const float*)d_in[3];
    const float* dlt = (const float*)d_in[4];
    const float* Q1  = (const float*)d_in[5];
    const float* Q2  = (const float*)d_in[6];
    const float* Q3  = (const float*)d_in[7];
    float* out = (float*)d_out;

    __half *xh, *VTh, *Ush, *Wth;
    float *W0, *W1;
    cudaGetSymbolAddress((void**)&xh,  g_xh);
    cudaGetSymbolAddress((void**)&VTh, g_VTh);
    cudaGetSymbolAddress((void**)&Ush, g_Ush);
    cudaGetSymbolAddress((void**)&Wth, g_Wth);
    cudaGetSymbolAddress((void**)&W0,  g_W0);
    cudaGetSymbolAddress((void**)&W1,  g_W1);

    cudaFuncSetAttribute(mma_gemm1,
                         cudaFuncAttributeMaxDynamicSharedMemorySize, GEMM_SMEM);
    cudaFuncSetAttribute(kron23_kernel,
                         cudaFuncAttributeMaxDynamicSharedMemorySize, 49152);

    // 1) x -> xh (fp16, unscaled)
    {
        size_t n4 = (size_t)SEQ_M * IN_F / 4;
        conv_scale_kernel<<<(unsigned)(n4 / 256), 256>>>(
            x, nullptr, nullptr, xh, n4, IN_F, 1.0f);
    }
    // 2) V [k][d] -> VTh [d][k] (x256)
    transpose_conv_kernel<<<dim3(IN_F / 32, IN_F / 32), dim3(32, 8)>>>(
        V, VTh, IN_F, IN_F, 256.0f);
    // 3) U[o][k]*relu(S[k]+delta[k]) -> Ush (x256)
    {
        size_t n4 = (size_t)IN_F * IN_F / 4;
        conv_scale_kernel<<<(unsigned)(n4 / 256), 256>>>(
            U, S, dlt, Ush, n4, IN_F, 256.0f);
    }
    // 4) W^T[d][o] = (VTh @ Ush^T) / 65536
    mma_gemm1<<<dim3(IN_F / 256, IN_F / 128), NTHR, GEMM_SMEM>>>(
        VTh, Ush, W0, IN_F, IN_F, IN_F, 1.0f / 65536.0f);

    // 5) Kronecker: fused Q3+Q2 (one round-trip), then Q1
    kron23_kernel<<<dim3(IN_F / 64, 16), 256, 49152>>>(W0, W1, Q2, Q3);
    kron_stage_kernel<<<dim3(IN_F / 256, 192), 256>>>(W1, W0, Q1, 16, 192);

    // 6) W_t [d][o] -> Wth [o][d] (x256)
    transpose_conv_kernel<<<dim3(IN_F / 32, IN_F / 32), dim3(32, 8)>>>(
        W0, Wth, IN_F, IN_F, 256.0f);

    // 7) out[m][o] = (xh @ Wth^T) / 256
    mma_gemm1<<<dim3(IN_F / 256, SEQ_M / 128), NTHR, GEMM_SMEM>>>(
        xh, Wth, out, SEQ_M, IN_F, IN_F, 1.0f / 256.0f);
}

// round 15
// speedup vs baseline: 11.3298x; 1.0086x over previous
#include <cuda_runtime.h>
#include <cuda_fp16.h>
#include <cstdint>
#include <cstddef>

// ---------------------------------------------------------------------------
// InjectedSODA_SVD: out = x @ ( (Q1⊗Q2⊗Q3) @ ((U*relu(S+delta)) @ V)^T )
//
// Pure fp16 1-term warp-MMA (m16n8k16 f16->f32), rel_err 4.15e-4 (measured).
// Weight-path operands pre-scaled x256 (exact power of two) to avoid fp16
// subnormals in W_t; epilogues divide it back out.
//
// R15 changes vs R14 (943us, tensor 78.3%):
//  1. mbar_wait: mbarrier.test_wait poll (149cyc/wait measured class) ->
//     mbarrier.try_wait.parity HW-sleep (90/60cyc). Two waits per warp per
//     chunk on both GEMMs.
//  2. Kron Q1 stage + W_t transpose + fp16 convert fused into one kernel
//     (same fmaf j-order -> bitwise identical), removing a 75MB round trip.
//  GEMM structure otherwise identical to R14.
// ---------------------------------------------------------------------------

#define IN_F   3072
#define SEQ_M  16384

// ---------------- scratch (device globals; allocation is forbidden) --------
__device__ __align__(1024) __half g_xh [(size_t)SEQ_M * IN_F];
__device__ __align__(1024) __half g_VTh[(size_t)IN_F * IN_F];
__device__ __align__(1024) __half g_Ush[(size_t)IN_F * IN_F];
__device__ __align__(1024) __half g_Wth[(size_t)IN_F * IN_F];
__device__ __align__(1024) float  g_W0[(size_t)IN_F * IN_F];
__device__ __align__(1024) float  g_W1[(size_t)IN_F * IN_F];

// ---------------- PTX helpers (base-target features only) -------------------
__device__ __forceinline__ uint32_t smem_u32(const void* p) {
    uint32_t a;
    asm("{ .reg .u64 t; cvta.to.shared.u64 t, %1; cvt.u32.u64 %0, t; }"
        : "=r"(a) : "l"(p));
    return a;
}
__device__ __forceinline__ uint32_t swz128(uint32_t o) {
    return o ^ ((o >> 3) & 0x70);
}
__device__ __forceinline__ void cp16(uint32_t dst, const void* src) {
    asm volatile("cp.async.cg.shared.global [%0], [%1], 16;"
                 :: "r"(dst), "l"(src));
}
__device__ __forceinline__ void ldsm4(uint32_t* r, uint32_t addr) {
    asm volatile("ldmatrix.sync.aligned.m8n8.x4.shared.b16 {%0,%1,%2,%3}, [%4];"
                 : "=r"(r[0]), "=r"(r[1]), "=r"(r[2]), "=r"(r[3])
                 : "r"(addr));
}
__device__ __forceinline__ void mma16816(float* c, const uint32_t* a,
                                         const uint32_t* b) {
    asm volatile(
        "mma.sync.aligned.m16n8k16.row.col.f32.f16.f16.f32 "
        "{%0,%1,%2,%3}, {%4,%5,%6,%7}, {%8,%9}, {%0,%1,%2,%3};"
        : "+f"(c[0]), "+f"(c[1]), "+f"(c[2]), "+f"(c[3])
        : "r"(a[0]), "r"(a[1]), "r"(a[2]), "r"(a[3]), "r"(b[0]), "r"(b[1]));
}
__device__ __forceinline__ void mbar_init(uint32_t a, uint32_t n) {
    asm volatile("mbarrier.init.shared.b64 [%0], %1;"
                 :: "r"(a), "r"(n) : "memory");
}
__device__ __forceinline__ void mbar_arrive(uint32_t a) {
    asm volatile("{\n\t.reg .b64 t;\n\tmbarrier.arrive.shared.b64 t, [%0];\n\t}"
                 :: "r"(a) : "memory");
}
__device__ __forceinline__ void cpasync_mbar_arrive(uint32_t a) {
    // .noinc: consume one pre-initialized arrival (default form deadlocks).
    asm volatile("cp.async.mbarrier.arrive.noinc.shared.b64 [%0];"
                 :: "r"(a) : "memory");
}
__device__ __forceinline__ void mbar_wait(uint32_t a, uint32_t parity) {
    // HW-sleep try_wait (90/60 cyc) instead of test_wait poll (149 cyc).
    asm volatile(
        "{\n\t.reg .pred P;\n\t"
        "WL_%=:\n\t"
        "mbarrier.try_wait.parity.shared::cta.b64 P, [%0], %1, 0x989680;\n\t"
        "@P bra.uni WD_%=;\n\t"
        "bra.uni WL_%=;\n\t"
        "WD_%=:\n\t}"
        :: "r"(a), "r"(parity) : "memory");
}

// ---------------------------------------------------------------------------
// scale(+optional per-col relu(S+D)) then fp16 convert
// ---------------------------------------------------------------------------
__global__ void conv_scale_kernel(const float* __restrict__ in,
                                  const float* __restrict__ S,
                                  const float* __restrict__ D,
                                  __half* __restrict__ out16,
                                  size_t n4, int cols, float scale)
{
    size_t i = (size_t)blockIdx.x * blockDim.x + threadIdx.x;
    if (i >= n4) return;
    float4 v = ((const float4*)in)[i];
    if (S) {
        int c = (int)((i * 4) % (size_t)cols);
        v.x *= fmaxf(S[c + 0] + D[c + 0], 0.0f);
        v.y *= fmaxf(S[c + 1] + D[c + 1], 0.0f);
        v.z *= fmaxf(S[c + 2] + D[c + 2], 0.0f);
        v.w *= fmaxf(S[c + 3] + D[c + 3], 0.0f);
    }
    v.x *= scale; v.y *= scale; v.z *= scale; v.w *= scale;
    ((__half2*)out16)[i * 2 + 0] =
        __halves2half2(__float2half_rn(v.x), __float2half_rn(v.y));
    ((__half2*)out16)[i * 2 + 1] =
        __halves2half2(__float2half_rn(v.z), __float2half_rn(v.w));
}

// ---------------------------------------------------------------------------
// transpose + scale + fp16 convert: in [NJ][NI] f32 -> [NI][NJ] fp16  (for V)
// ---------------------------------------------------------------------------
__global__ void transpose_conv_kernel(const float* __restrict__ in,
                                      __half* __restrict__ out16,
                                      int NJ, int NI, float scale)
{
    __shared__ float t[32][33];
    const int i0 = blockIdx.y * 32;
    const int j0 = blockIdx.x * 32;
    const int x = threadIdx.x, y = threadIdx.y;
#pragma unroll
    for (int r = 0; r < 4; r++)
        t[y + 8 * r][x] = in[(size_t)(j0 + y + 8 * r) * NI + (i0 + x)];
    __syncthreads();
#pragma unroll
    for (int r = 0; r < 4; r++) {
        const int i = i0 + y + 8 * r;
        out16[(size_t)i * NJ + (j0 + x)] =
            __float2half_rn(t[x][y + 8 * r] * scale);
    }
}

// ---------------------------------------------------------------------------
// Fused Kronecker Q3+Q2 stages, smem-resident (bitwise identical to the two
// staged passes). d = (j1*16 + j2)*12 + j3; block: j1 = blockIdx.y (0..15),
// o-tile = 64 cols.
// ---------------------------------------------------------------------------
__global__ void kron23_kernel(const float* __restrict__ in,
                              float* __restrict__ out,
                              const float* __restrict__ Q2,
                              const float* __restrict__ Q3)
{
    extern __shared__ float t[];              // [192][64] = 48 KB
    __shared__ float sQ2[256], sQ3[144];
    const int tid = threadIdx.x;              // 256
    const int oc = tid & 63, g = tid >> 6;    // col 0..63, group 0..3
    if (tid < 144) sQ3[tid] = Q3[tid];
    sQ2[tid] = Q2[tid];
    const size_t base = (size_t)blockIdx.y * 192 * IN_F + blockIdx.x * 64;

    for (int r = g; r < 192; r += 4)
        t[r * 64 + oc] = in[base + (size_t)r * IN_F + oc];
    __syncthreads();

    // pass 1 (Q3)
    for (int c2 = g; c2 < 16; c2 += 4) {
        float v[12], o[12];
#pragma unroll
        for (int j = 0; j < 12; j++) v[j] = t[(c2 * 12 + j) * 64 + oc];
#pragma unroll
        for (int i = 0; i < 12; i++) {
            float acc = 0.0f;
#pragma unroll
            for (int j = 0; j < 12; j++)
                acc = fmaf(sQ3[i * 12 + j], v[j], acc);
            o[i] = acc;
        }
#pragma unroll
        for (int i = 0; i < 12; i++) t[(c2 * 12 + i) * 64 + oc] = o[i];
    }
    __syncthreads();

    // pass 2 (Q2)
    for (int i3 = g * 3; i3 < g * 3 + 3; i3++) {
        float v[16];
#pragma unroll
        for (int j = 0; j < 16; j++) v[j] = t[(j * 12 + i3) * 64 + oc];
#pragma unroll
        for (int i2 = 0; i2 < 16; i2++) {
            float acc = 0.0f;
#pragma unroll
            for (int j = 0; j < 16; j++)
                acc = fmaf(sQ2[i2 * 16 + j], v[j], acc);
            out[base + (size_t)(i2 * 12 + i3) * IN_F + oc] = acc;
        }
    }
}

// ---------------------------------------------------------------------------
// Fused Kronecker Q1 stage + transpose + fp16 convert (x256):
//   Wth[o][i1*192 + c] = fp16( 256 * sum_j1 Q1[i1*16+j1] * W1[j1*192+c][o] )
// Block: (o-tile 32, c-tile 32); grid (96, 6); 256 threads.
// smem: sIn f32[16][32][32] (64KB) + sOut f32[16][32][33] (67.6KB).
// Same fmaf j-order as the staged kron + same scale-then-convert -> bitwise
// identical to the old kron_stage(Q1) + transpose_conv sequence.
// ---------------------------------------------------------------------------
#define K1T_SMEM (16 * 32 * 32 * 4 + 16 * 32 * 33 * 4)   // 133,120 B

__global__ void kron1t_kernel(const float* __restrict__ in,
                              __half* __restrict__ out16,
                              const float* __restrict__ Q1)
{
    extern __shared__ float sm[];
    float* sIn  = sm;                         // [16][32][32]
    float* sOut = sm + 16 * 32 * 32;          // [16][32][33]
    __shared__ float sQ1[256];
    const int tid = threadIdx.x;
    const int o0 = blockIdx.x * 32;
    const int c0 = blockIdx.y * 32;
    sQ1[tid] = Q1[tid];

    // load: 512 rows (j1*192 + c0+c) x 32 cols (o0..o0+31), 16 float4/thread
#pragma unroll
    for (int i = 0; i < 16; i++) {
        int idx = tid + i * 256;
        int rl = idx >> 3;                    // 0..511
        int j1 = rl >> 5, c = rl & 31;
        int col4 = idx & 7;
        *(float4*)&sIn[(j1 * 32 + c) * 32 + col4 * 4] =
            *(const float4*)(in + (size_t)(j1 * 192 + c0 + c) * IN_F
                             + o0 + col4 * 4);
    }
    __syncthreads();

    // contract: thread owns 4 (c,o) cells, 16 i1 outputs each
#pragma unroll
    for (int p = 0; p < 4; p++) {
        int idx = tid + p * 256;
        int o = idx & 31, c = (idx >> 5) & 31;
        float v[16];
#pragma unroll
        for (int j = 0; j < 16; j++) v[j] = sIn[(j * 32 + c) * 32 + o];
#pragma unroll
        for (int i1 = 0; i1 < 16; i1++) {
            float acc = 0.0f;
#pragma unroll
            for (int j = 0; j < 16; j++)
                acc = fmaf(sQ1[i1 * 16 + j], v[j], acc);
            sOut[(i1 * 32 + c) * 33 + o] = acc;
        }
    }
    __syncthreads();

    // write-out: 512 segments (i1,o) of 32 c-values -> 64B vector stores
#pragma unroll
    for (int r = 0; r < 2; r++) {
        int s = tid + r * 256;
        int i1 = s >> 5, o = s & 31;
        uint32_t pk[16];
#pragma unroll
        for (int cc = 0; cc < 16; cc++) {
            float a = sOut[(i1 * 32 + 2 * cc + 0) * 33 + o] * 256.0f;
            float b = sOut[(i1 * 32 + 2 * cc + 1) * 33 + o] * 256.0f;
            __half2 h = __halves2half2(__float2half_rn(a), __float2half_rn(b));
            pk[cc] = *(uint32_t*)&h;
        }
        __half* gp = out16 + (size_t)(o0 + o) * IN_F + i1 * 192 + c0;
#pragma unroll
        for (int q = 0; q < 4; q++)
            *(uint4*)(gp + q * 8) = *(uint4*)&pk[q * 4];
    }
}

// ---------------------------------------------------------------------------
// Warp-MMA 1-term fp16 GEMM: C[m][n] = out_scale * sum_k A[m][k]*B[n][k]
// Block 128x256, K-chunk 64 (128B swizzled rows), 4-stage mbarrier pipeline.
// 256 threads: 8 warps (2M x 4N), warp tile 64x64. M,N,K mult of 128/256/64.
// ---------------------------------------------------------------------------
#define GKCH       64
#define SOF_A      0
#define SOF_B      16384                   // A: 128 rows x 128 B
#define STAGE_B    49152                   // + B: 256 rows x 128 B = 48 KB
#define NSTAGE     4
#define GEMM_SMEM  (NSTAGE * STAGE_B + 1024)   // ~193 KB
#define NTHR       256

__device__ __forceinline__ void load_tiles(uint32_t sb,
                                           const char* pA, const char* pB,
                                           size_t ldb, size_t gbase, int tid)
{
    // A tile: 1024 x 16B  (4 per thread)
#pragma unroll
    for (int i = 0; i < 4; i++) {
        int idx = tid + i * NTHR;
        int row = idx >> 3;
        uint32_t c16 = (uint32_t)(idx & 7) << 4;
        uint32_t so = swz128((uint32_t)row * 128u + c16);
        cp16(sb + SOF_A + so, pA + (size_t)row * ldb + gbase + c16);
    }
    // B tile: 2048 x 16B  (8 per thread)
#pragma unroll
    for (int i = 0; i < 8; i++) {
        int idx = tid + i * NTHR;
        int row = idx >> 3;
        uint32_t c16 = (uint32_t)(idx & 7) << 4;
        uint32_t so = swz128((uint32_t)row * 128u + c16);
        cp16(sb + SOF_B + so, pB + (size_t)row * ldb + gbase + c16);
    }
}

__global__ __launch_bounds__(NTHR, 1)
void mma_gemm1(const __half* __restrict__ A,
               const __half* __restrict__ B,
               float* __restrict__ C, int M, int N, int K, float out_scale)
{
    extern __shared__ char dynsmem[];
    __shared__ __align__(8) unsigned long long s_bar[2 * NSTAGE];

    const int tid = threadIdx.x;
    const uint32_t smem = (smem_u32(dynsmem) + 1023u) & ~1023u;
    const uint32_t barb = smem_u32(s_bar);   // full[s]=barb+8s, empty[s]=barb+32+8s

    const int w = tid >> 5, lane = tid & 31;
    const int m0 = (w >> 2) * 64;          // 2 M-slabs of 64
    const int n0 = (w & 3) * 64;           // 4 N-slabs of 64

    // ldmatrix lane patterns
    const int rowA  = lane & 15;
    const uint32_t kselA = (uint32_t)(lane >> 4) << 4;       // 0 or 16
    const int rowB  = (lane & 7) + ((lane >> 4) << 3);
    const uint32_t kselB = (uint32_t)((lane >> 3) & 1) << 4; // 0 or 16

    const size_t ldb = (size_t)K * 2;
    const char* pA = (const char*)A + (size_t)blockIdx.y * 128 * ldb;
    const char* pB = (const char*)B + (size_t)blockIdx.x * 256 * ldb;

    const uint32_t aOff = (uint32_t)(m0 + rowA) * 128u + kselA;
    const uint32_t bOff = (uint32_t)(n0 + rowB) * 128u + kselB;

    // barrier init: full count=NTHR (cp.async arrivals), empty count=8 warps
    if (tid == 0) {
#pragma unroll
        for (int s = 0; s < NSTAGE; s++) {
            mbar_init(barb + 8u * s, NTHR);
            mbar_init(barb + 32u + 8u * s, 8);
        }
    }
    __syncthreads();

    float acc[4][8][4];
#pragma unroll
    for (int a = 0; a < 4; a++)
#pragma unroll
        for (int b = 0; b < 8; b++)
#pragma unroll
            for (int c = 0; c < 4; c++) acc[a][b][c] = 0.0f;

    const int KT = K / GKCH;

    // prologue: chunks 0..2 -> stages 0..2 (no empty wait: first use)
#pragma unroll
    for (int c = 0; c < NSTAGE - 1; c++) {
        load_tiles(smem + c * STAGE_B, pA, pB, ldb, (size_t)c * (GKCH * 2), tid);
        cpasync_mbar_arrive(barb + 8u * c);
    }

    for (int kc = 0; kc < KT; kc++) {
        const uint32_t s  = (uint32_t)kc & (NSTAGE - 1);
        const uint32_t sb = smem + s * STAGE_B;

        // consumer: wait chunk kc's data
        mbar_wait(barb + 8u * s, (uint32_t)(kc >> 2) & 1u);

#pragma unroll
        for (int kk = 0; kk < 4; kk++) {
            const uint32_t kb = (uint32_t)kk * 32;
            uint32_t af[4][4], bf[4][4];
#pragma unroll
            for (int mi = 0; mi < 4; mi++)
                ldsm4(af[mi], sb + SOF_A + swz128(aOff + (uint32_t)mi * 2048 + kb));
#pragma unroll
            for (int j = 0; j < 4; j++)
                ldsm4(bf[j], sb + SOF_B + swz128(bOff + (uint32_t)j * 2048 + kb));
#pragma unroll
            for (int mi = 0; mi < 4; mi++)
#pragma unroll
                for (int ni = 0; ni < 8; ni++)
                    mma16816(acc[mi][ni], af[mi], &bf[ni >> 1][(ni & 1) * 2]);
        }

        // this warp is done reading stage s
        __syncwarp();
        if (lane == 0) mbar_arrive(barb + 32u + 8u * s);

        // producer (off critical path): issue loads for chunk kc+3
        const int kn = kc + NSTAGE - 1;
        if (kn < KT) {
            const uint32_t sn = (uint32_t)kn & (NSTAGE - 1);
            if (kn >= NSTAGE)   // stage previously held chunk kn-4
                mbar_wait(barb + 32u + 8u * sn,
                          (uint32_t)((kn - NSTAGE) >> 2) & 1u);
            load_tiles(smem + sn * STAGE_B, pA, pB, ldb,
                       (size_t)kn * (GKCH * 2), tid);
            cpasync_mbar_arrive(barb + 8u * sn);
        }
    }

    // epilogue: scale + direct f32 stores
    const int g = lane >> 2, t2 = (lane & 3) * 2;
    const size_t rbase = (size_t)blockIdx.y * 128 + m0;
    const size_t cbase = (size_t)blockIdx.x * 256 + n0;
#pragma unroll
    for (int mi = 0; mi < 4; mi++) {
#pragma unroll
        for (int ni = 0; ni < 8; ni++) {
            float* p0 = C + (rbase + mi * 16 + g) * (size_t)N
                          + cbase + ni * 8 + t2;
            float* p1 = p0 + 8 * (size_t)N;
            *(float2*)p0 = make_float2(acc[mi][ni][0] * out_scale,
                                       acc[mi][ni][1] * out_scale);
            *(float2*)p1 = make_float2(acc[mi][ni][2] * out_scale,
                                       acc[mi][ni][3] * out_scale);
        }
    }
}

// ---------------------------------------------------------------------------
// Launch
// ---------------------------------------------------------------------------
extern "C" void kernel_launch(void* const* d_in, const int* in_sizes, int n_in,
                              void* d_out, int out_size)
{
    (void)in_sizes; (void)n_in; (void)out_size;
    const float* x   = (const float*)d_in[0];
    const float* U   = (const float*)d_in[1];
    const float* S   = (const float*)d_in[2];
    const float* V   = (const float*)d_in[3];
    const float* dlt = (const float*)d_in[4];
    const float* Q1  = (const float*)d_in[5];
    const float* Q2  = (const float*)d_in[6];
    const float* Q3  = (const float*)d_in[7];
    float* out = (float*)d_out;

    __half *xh, *VTh, *Ush, *Wth;
    float *W0, *W1;
    cudaGetSymbolAddress((void**)&xh,  g_xh);
    cudaGetSymbolAddress((void**)&VTh, g_VTh);
    cudaGetSymbolAddress((void**)&Ush, g_Ush);
    cudaGetSymbolAddress((void**)&Wth, g_Wth);
    cudaGetSymbolAddress((void**)&W0,  g_W0);
    cudaGetSymbolAddress((void**)&W1,  g_W1);

    cudaFuncSetAttribute(mma_gemm1,
                         cudaFuncAttributeMaxDynamicSharedMemorySize, GEMM_SMEM);
    cudaFuncSetAttribute(kron23_kernel,
                         cudaFuncAttributeMaxDynamicSharedMemorySize, 49152);
    cudaFuncSetAttribute(kron1t_kernel,
                         cudaFuncAttributeMaxDynamicSharedMemorySize, K1T_SMEM);

    // 1) x -> xh (fp16, unscaled)
    {
        size_t n4 = (size_t)SEQ_M * IN_F / 4;
        conv_scale_kernel<<<(unsigned)(n4 / 256), 256>>>(
            x, nullptr, nullptr, xh, n4, IN_F, 1.0f);
    }
    // 2) V [k][d] -> VTh [d][k] (x256)
    transpose_conv_kernel<<<dim3(IN_F / 32, IN_F / 32), dim3(32, 8)>>>(
        V, VTh, IN_F, IN_F, 256.0f);
    // 3) U[o][k]*relu(S[k]+delta[k]) -> Ush (x256)
    {
        size_t n4 = (size_t)IN_F * IN_F / 4;
        conv_scale_kernel<<<(unsigned)(n4 / 256), 256>>>(
            U, S, dlt, Ush, n4, IN_F, 256.0f);
    }
    // 4) W^T[d][o] = (VTh @ Ush^T) / 65536
    mma_gemm1<<<dim3(IN_F / 256, IN_F / 128), NTHR, GEMM_SMEM>>>(
        VTh, Ush, W0, IN_F, IN_F, IN_F, 1.0f / 65536.0f);

    // 5) Kronecker: fused Q3+Q2, then fused Q1+transpose+convert (x256)
    kron23_kernel<<<dim3(IN_F / 64, 16), 256, 49152>>>(W0, W1, Q2, Q3);
    kron1t_kernel<<<dim3(IN_F / 32, 192 / 32), 256, K1T_SMEM>>>(W1, Wth, Q1);

    // 6) out[m][o] = (xh @ Wth^T) / 256
    mma_gemm1<<<dim3(IN_F / 256, SEQ_M / 128), NTHR, GEMM_SMEM>>>(
        xh, Wth, out, SEQ_M, IN_F, IN_F, 1.0f / 256.0f);
}

// round 17
// speedup vs baseline: 11.5166x; 1.0165x over previous
#include <cuda_runtime.h>
#include <cuda_fp16.h>
#include <cstdint>
#include <cstddef>

// ---------------------------------------------------------------------------
// InjectedSODA_SVD: out = x @ ( (Q1⊗Q2⊗Q3) @ ((U*relu(S+delta)) @ V)^T )
//
// Pure fp16 1-term warp-MMA (m16n8k16 f16->f32), rel_err 4.15e-4 (measured).
// Weight-path operands pre-scaled x256 (exact power of two) to avoid fp16
// subnormals in W_t; epilogues divide it back out.
//
// R16 changes vs R15 (935us):
//  1. GEMM is PERSISTENT: grid = #SMs, each CTA walks its tiles with ONE
//     continuous mbarrier ring across tile boundaries (global chunk counter
//     keeps the s=g&3 / parity algebra; producer advances tile pointers on
//     K-wrap). Pipeline fill/drain paid once per CTA, not once per tile;
//     per-tile epilogue overlaps the next tile's loads.
//  2. mbar_wait reverted to R14's test_wait+nanosleep (best measured; the
//     R15 try_wait swap was neutral-to-negative).
//  Per-tile accumulation order unchanged -> rel_err must stay 4.148e-4.
// ---------------------------------------------------------------------------

#define IN_F   3072
#define SEQ_M  16384

// ---------------- scratch (device globals; allocation is forbidden) --------
__device__ __align__(1024) __half g_xh [(size_t)SEQ_M * IN_F];
__device__ __align__(1024) __half g_VTh[(size_t)IN_F * IN_F];
__device__ __align__(1024) __half g_Ush[(size_t)IN_F * IN_F];
__device__ __align__(1024) __half g_Wth[(size_t)IN_F * IN_F];
__device__ __align__(1024) float  g_W0[(size_t)IN_F * IN_F];
__device__ __align__(1024) float  g_W1[(size_t)IN_F * IN_F];

// ---------------- PTX helpers (base-target features only) -------------------
__device__ __forceinline__ uint32_t smem_u32(const void* p) {
    uint32_t a;
    asm("{ .reg .u64 t; cvta.to.shared.u64 t, %1; cvt.u32.u64 %0, t; }"
        : "=r"(a) : "l"(p));
    return a;
}
__device__ __forceinline__ uint32_t swz128(uint32_t o) {
    return o ^ ((o >> 3) & 0x70);
}
__device__ __forceinline__ void cp16(uint32_t dst, const void* src) {
    asm volatile("cp.async.cg.shared.global [%0], [%1], 16;"
                 :: "r"(dst), "l"(src));
}
__device__ __forceinline__ void ldsm4(uint32_t* r, uint32_t addr) {
    asm volatile("ldmatrix.sync.aligned.m8n8.x4.shared.b16 {%0,%1,%2,%3}, [%4];"
                 : "=r"(r[0]), "=r"(r[1]), "=r"(r[2]), "=r"(r[3])
                 : "r"(addr));
}
__device__ __forceinline__ void mma16816(float* c, const uint32_t* a,
                                         const uint32_t* b) {
    asm volatile(
        "mma.sync.aligned.m16n8k16.row.col.f32.f16.f16.f32 "
        "{%0,%1,%2,%3}, {%4,%5,%6,%7}, {%8,%9}, {%0,%1,%2,%3};"
        : "+f"(c[0]), "+f"(c[1]), "+f"(c[2]), "+f"(c[3])
        : "r"(a[0]), "r"(a[1]), "r"(a[2]), "r"(a[3]), "r"(b[0]), "r"(b[1]));
}
__device__ __forceinline__ void mbar_init(uint32_t a, uint32_t n) {
    asm volatile("mbarrier.init.shared.b64 [%0], %1;"
                 :: "r"(a), "r"(n) : "memory");
}
__device__ __forceinline__ void mbar_arrive(uint32_t a) {
    asm volatile("{\n\t.reg .b64 t;\n\tmbarrier.arrive.shared.b64 t, [%0];\n\t}"
                 :: "r"(a) : "memory");
}
__device__ __forceinline__ void cpasync_mbar_arrive(uint32_t a) {
    // .noinc: consume one pre-initialized arrival (default form deadlocks).
    asm volatile("cp.async.mbarrier.arrive.noinc.shared.b64 [%0];"
                 :: "r"(a) : "memory");
}
__device__ __forceinline__ void mbar_wait(uint32_t a, uint32_t parity) {
    uint32_t done;
    asm volatile(
        "{\n\t.reg .pred P;\n\t"
        "mbarrier.test_wait.parity.shared.b64 P, [%1], %2;\n\t"
        "selp.b32 %0, 1, 0, P;\n\t}"
        : "=r"(done) : "r"(a), "r"(parity) : "memory");
    while (!done) {
        asm volatile("nanosleep.u32 32;");
        asm volatile(
            "{\n\t.reg .pred P;\n\t"
            "mbarrier.test_wait.parity.shared.b64 P, [%1], %2;\n\t"
            "selp.b32 %0, 1, 0, P;\n\t}"
            : "=r"(done) : "r"(a), "r"(parity) : "memory");
    }
}

// ---------------------------------------------------------------------------
// scale(+optional per-col relu(S+D)) then fp16 convert
// ---------------------------------------------------------------------------
__global__ void conv_scale_kernel(const float* __restrict__ in,
                                  const float* __restrict__ S,
                                  const float* __restrict__ D,
                                  __half* __restrict__ out16,
                                  size_t n4, int cols, float scale)
{
    size_t i = (size_t)blockIdx.x * blockDim.x + threadIdx.x;
    if (i >= n4) return;
    float4 v = ((const float4*)in)[i];
    if (S) {
        int c = (int)((i * 4) % (size_t)cols);
        v.x *= fmaxf(S[c + 0] + D[c + 0], 0.0f);
        v.y *= fmaxf(S[c + 1] + D[c + 1], 0.0f);
        v.z *= fmaxf(S[c + 2] + D[c + 2], 0.0f);
        v.w *= fmaxf(S[c + 3] + D[c + 3], 0.0f);
    }
    v.x *= scale; v.y *= scale; v.z *= scale; v.w *= scale;
    ((__half2*)out16)[i * 2 + 0] =
        __halves2half2(__float2half_rn(v.x), __float2half_rn(v.y));
    ((__half2*)out16)[i * 2 + 1] =
        __halves2half2(__float2half_rn(v.z), __float2half_rn(v.w));
}

// ---------------------------------------------------------------------------
// transpose + scale + fp16 convert: in [NJ][NI] f32 -> [NI][NJ] fp16  (for V)
// ---------------------------------------------------------------------------
__global__ void transpose_conv_kernel(const float* __restrict__ in,
                                      __half* __restrict__ out16,
                                      int NJ, int NI, float scale)
{
    __shared__ float t[32][33];
    const int i0 = blockIdx.y * 32;
    const int j0 = blockIdx.x * 32;
    const int x = threadIdx.x, y = threadIdx.y;
#pragma unroll
    for (int r = 0; r < 4; r++)
        t[y + 8 * r][x] = in[(size_t)(j0 + y + 8 * r) * NI + (i0 + x)];
    __syncthreads();
#pragma unroll
    for (int r = 0; r < 4; r++) {
        const int i = i0 + y + 8 * r;
        out16[(size_t)i * NJ + (j0 + x)] =
            __float2half_rn(t[x][y + 8 * r] * scale);
    }
}

// ---------------------------------------------------------------------------
// Fused Kronecker Q3+Q2 stages, smem-resident (bitwise identical to the two
// staged passes). d = (j1*16 + j2)*12 + j3; block: j1 = blockIdx.y (0..15),
// o-tile = 64 cols.
// ---------------------------------------------------------------------------
__global__ void kron23_kernel(const float* __restrict__ in,
                              float* __restrict__ out,
                              const float* __restrict__ Q2,
                              const float* __restrict__ Q3)
{
    extern __shared__ float t[];              // [192][64] = 48 KB
    __shared__ float sQ2[256], sQ3[144];
    const int tid = threadIdx.x;              // 256
    const int oc = tid & 63, g = tid >> 6;    // col 0..63, group 0..3
    if (tid < 144) sQ3[tid] = Q3[tid];
    sQ2[tid] = Q2[tid];
    const size_t base = (size_t)blockIdx.y * 192 * IN_F + blockIdx.x * 64;

    for (int r = g; r < 192; r += 4)
        t[r * 64 + oc] = in[base + (size_t)r * IN_F + oc];
    __syncthreads();

    // pass 1 (Q3)
    for (int c2 = g; c2 < 16; c2 += 4) {
        float v[12], o[12];
#pragma unroll
        for (int j = 0; j < 12; j++) v[j] = t[(c2 * 12 + j) * 64 + oc];
#pragma unroll
        for (int i = 0; i < 12; i++) {
            float acc = 0.0f;
#pragma unroll
            for (int j = 0; j < 12; j++)
                acc = fmaf(sQ3[i * 12 + j], v[j], acc);
            o[i] = acc;
        }
#pragma unroll
        for (int i = 0; i < 12; i++) t[(c2 * 12 + i) * 64 + oc] = o[i];
    }
    __syncthreads();

    // pass 2 (Q2)
    for (int i3 = g * 3; i3 < g * 3 + 3; i3++) {
        float v[16];
#pragma unroll
        for (int j = 0; j < 16; j++) v[j] = t[(j * 12 + i3) * 64 + oc];
#pragma unroll
        for (int i2 = 0; i2 < 16; i2++) {
            float acc = 0.0f;
#pragma unroll
            for (int j = 0; j < 16; j++)
                acc = fmaf(sQ2[i2 * 16 + j], v[j], acc);
            out[base + (size_t)(i2 * 12 + i3) * IN_F + oc] = acc;
        }
    }
}

// ---------------------------------------------------------------------------
// Fused Kronecker Q1 stage + transpose + fp16 convert (x256):
//   Wth[o][i1*192 + c] = fp16( 256 * sum_j1 Q1[i1*16+j1] * W1[j1*192+c][o] )
// ---------------------------------------------------------------------------
#define K1T_SMEM (16 * 32 * 32 * 4 + 16 * 32 * 33 * 4)   // 133,120 B

__global__ void kron1t_kernel(const float* __restrict__ in,
                              __half* __restrict__ out16,
                              const float* __restrict__ Q1)
{
    extern __shared__ float sm[];
    float* sIn  = sm;                         // [16][32][32]
    float* sOut = sm + 16 * 32 * 32;          // [16][32][33]
    __shared__ float sQ1[256];
    const int tid = threadIdx.x;
    const int o0 = blockIdx.x * 32;
    const int c0 = blockIdx.y * 32;
    sQ1[tid] = Q1[tid];

#pragma unroll
    for (int i = 0; i < 16; i++) {
        int idx = tid + i * 256;
        int rl = idx >> 3;
        int j1 = rl >> 5, c = rl & 31;
        int col4 = idx & 7;
        *(float4*)&sIn[(j1 * 32 + c) * 32 + col4 * 4] =
            *(const float4*)(in + (size_t)(j1 * 192 + c0 + c) * IN_F
                             + o0 + col4 * 4);
    }
    __syncthreads();

#pragma unroll
    for (int p = 0; p < 4; p++) {
        int idx = tid + p * 256;
        int o = idx & 31, c = (idx >> 5) & 31;
        float v[16];
#pragma unroll
        for (int j = 0; j < 16; j++) v[j] = sIn[(j * 32 + c) * 32 + o];
#pragma unroll
        for (int i1 = 0; i1 < 16; i1++) {
            float acc = 0.0f;
#pragma unroll
            for (int j = 0; j < 16; j++)
                acc = fmaf(sQ1[i1 * 16 + j], v[j], acc);
            sOut[(i1 * 32 + c) * 33 + o] = acc;
        }
    }
    __syncthreads();

#pragma unroll
    for (int r = 0; r < 2; r++) {
        int s = tid + r * 256;
        int i1 = s >> 5, o = s & 31;
        uint32_t pk[16];
#pragma unroll
        for (int cc = 0; cc < 16; cc++) {
            float a = sOut[(i1 * 32 + 2 * cc + 0) * 33 + o] * 256.0f;
            float b = sOut[(i1 * 32 + 2 * cc + 1) * 33 + o] * 256.0f;
            __half2 h = __halves2half2(__float2half_rn(a), __float2half_rn(b));
            pk[cc] = *(uint32_t*)&h;
        }
        __half* gp = out16 + (size_t)(o0 + o) * IN_F + i1 * 192 + c0;
#pragma unroll
        for (int q = 0; q < 4; q++)
            *(uint4*)(gp + q * 8) = *(uint4*)&pk[q * 4];
    }
}

// ---------------------------------------------------------------------------
// PERSISTENT warp-MMA 1-term fp16 GEMM:
//   C[m][n] = out_scale * sum_k A[m][k]*B[n][k]
// Tile 128x256, K-chunk 64 (128B swizzled rows), 4-stage mbarrier ring that
// runs CONTINUOUSLY across the CTA's tile list (global chunk counter g keeps
// s=g&3 / parity (g>>2)&1). 256 threads: 8 warps (2M x 4N), warp tile 64x64.
// M,N,K multiples of 128/256/64.
// ---------------------------------------------------------------------------
#define GKCH       64
#define SOF_A      0
#define SOF_B      16384                   // A: 128 rows x 128 B
#define STAGE_B    49152                   // + B: 256 rows x 128 B = 48 KB
#define NSTAGE     4
#define GEMM_SMEM  (NSTAGE * STAGE_B + 1024)   // ~193 KB
#define NTHR       256

__device__ __forceinline__ void load_tiles(uint32_t sb,
                                           const char* pA, const char* pB,
                                           size_t ldb, size_t gbase, int tid)
{
    // A tile: 1024 x 16B  (4 per thread)
#pragma unroll
    for (int i = 0; i < 4; i++) {
        int idx = tid + i * NTHR;
        int row = idx >> 3;
        uint32_t c16 = (uint32_t)(idx & 7) << 4;
        uint32_t so = swz128((uint32_t)row * 128u + c16);
        cp16(sb + SOF_A + so, pA + (size_t)row * ldb + gbase + c16);
    }
    // B tile: 2048 x 16B  (8 per thread)
#pragma unroll
    for (int i = 0; i < 8; i++) {
        int idx = tid + i * NTHR;
        int row = idx >> 3;
        uint32_t c16 = (uint32_t)(idx & 7) << 4;
        uint32_t so = swz128((uint32_t)row * 128u + c16);
        cp16(sb + SOF_B + so, pB + (size_t)row * ldb + gbase + c16);
    }
}

__global__ __launch_bounds__(NTHR, 1)
void mma_gemm_pers(const __half* __restrict__ A,
                   const __half* __restrict__ B,
                   float* __restrict__ C, int M, int N, int K,
                   float out_scale, int ntiles, int ntx)
{
    extern __shared__ char dynsmem[];
    __shared__ __align__(8) unsigned long long s_bar[2 * NSTAGE];

    const int tid = threadIdx.x;
    const uint32_t smem = (smem_u32(dynsmem) + 1023u) & ~1023u;
    const uint32_t barb = smem_u32(s_bar);   // full[s]=barb+8s, empty[s]=barb+32+8s

    const int w = tid >> 5, lane = tid & 31;
    const int m0 = (w >> 2) * 64;          // 2 M-slabs of 64
    const int n0 = (w & 3) * 64;           // 4 N-slabs of 64

    const int rowA  = lane & 15;
    const uint32_t kselA = (uint32_t)(lane >> 4) << 4;       // 0 or 16
    const int rowB  = (lane & 7) + ((lane >> 4) << 3);
    const uint32_t kselB = (uint32_t)((lane >> 3) & 1) << 4; // 0 or 16

    const size_t ldb = (size_t)K * 2;
    const uint32_t aOff = (uint32_t)(m0 + rowA) * 128u + kselA;
    const uint32_t bOff = (uint32_t)(n0 + rowB) * 128u + kselB;

    if (tid == 0) {
#pragma unroll
        for (int s = 0; s < NSTAGE; s++) {
            mbar_init(barb + 8u * s, NTHR);
            mbar_init(barb + 32u + 8u * s, 8);
        }
    }
    __syncthreads();

    const int t0 = blockIdx.x;
    if (t0 >= ntiles) return;
    const int KT = K / GKCH;
    const int ncta = (ntiles - 1 - t0) / gridDim.x + 1;
    const int total = ncta * KT;             // chunks this CTA will stream

    // producer state
    int p_tile = t0, p_kc = 0, gp = 0;
    const char* pA = (const char*)A + (size_t)(p_tile / ntx) * 128 * ldb;
    const char* pB = (const char*)B + (size_t)(p_tile % ntx) * 256 * ldb;

    // prologue: fill NSTAGE-1 stages
#pragma unroll
    for (int c = 0; c < NSTAGE - 1; c++) {
        if (gp < total) {
            load_tiles(smem + (uint32_t)(gp & 3) * STAGE_B, pA, pB, ldb,
                       (size_t)p_kc * (GKCH * 2), tid);
            cpasync_mbar_arrive(barb + 8u * (uint32_t)(gp & 3));
            gp++;
            if (++p_kc == KT) {
                p_kc = 0; p_tile += gridDim.x;
                if (p_tile < ntiles) {
                    pA = (const char*)A + (size_t)(p_tile / ntx) * 128 * ldb;
                    pB = (const char*)B + (size_t)(p_tile % ntx) * 256 * ldb;
                }
            }
        }
    }

    float acc[4][8][4];
#pragma unroll
    for (int a = 0; a < 4; a++)
#pragma unroll
        for (int b = 0; b < 8; b++)
#pragma unroll
            for (int c = 0; c < 4; c++) acc[a][b][c] = 0.0f;

    int g = 0;
    for (int t = t0; t < ntiles; t += gridDim.x) {
        for (int kc = 0; kc < KT; kc++, g++) {
            const uint32_t s  = (uint32_t)(g & 3);
            const uint32_t sb = smem + s * STAGE_B;

            // consumer: wait chunk g's data
            mbar_wait(barb + 8u * s, (uint32_t)(g >> 2) & 1u);

#pragma unroll
            for (int kk = 0; kk < 4; kk++) {
                const uint32_t kb = (uint32_t)kk * 32;
                uint32_t af[4][4], bf[4][4];
#pragma unroll
                for (int mi = 0; mi < 4; mi++)
                    ldsm4(af[mi], sb + SOF_A + swz128(aOff + (uint32_t)mi * 2048 + kb));
#pragma unroll
                for (int j = 0; j < 4; j++)
                    ldsm4(bf[j], sb + SOF_B + swz128(bOff + (uint32_t)j * 2048 + kb));
#pragma unroll
                for (int mi = 0; mi < 4; mi++)
#pragma unroll
                    for (int ni = 0; ni < 8; ni++)
                        mma16816(acc[mi][ni], af[mi], &bf[ni >> 1][(ni & 1) * 2]);
            }

            __syncwarp();
            if (lane == 0) mbar_arrive(barb + 32u + 8u * s);

            // producer: stream the next chunk (may belong to a later tile)
            if (gp < total) {
                const uint32_t sn = (uint32_t)(gp & 3);
                if (gp >= NSTAGE)
                    mbar_wait(barb + 32u + 8u * sn,
                              (uint32_t)((gp - NSTAGE) >> 2) & 1u);
                load_tiles(smem + sn * STAGE_B, pA, pB, ldb,
                           (size_t)p_kc * (GKCH * 2), tid);
                cpasync_mbar_arrive(barb + 8u * sn);
                gp++;
                if (++p_kc == KT) {
                    p_kc = 0; p_tile += gridDim.x;
                    if (p_tile < ntiles) {
                        pA = (const char*)A + (size_t)(p_tile / ntx) * 128 * ldb;
                        pB = (const char*)B + (size_t)(p_tile % ntx) * 256 * ldb;
                    }
                }
            }
        }

        // epilogue for tile t (overlaps the ring already loading next tile)
        {
            const int ty = t / ntx, tx = t % ntx;
            const int gg = lane >> 2, t2 = (lane & 3) * 2;
            const size_t rbase = (size_t)ty * 128 + m0;
            const size_t cbase = (size_t)tx * 256 + n0;
#pragma unroll
            for (int mi = 0; mi < 4; mi++) {
#pragma unroll
                for (int ni = 0; ni < 8; ni++) {
                    float* p0 = C + (rbase + mi * 16 + gg) * (size_t)N
                                  + cbase + ni * 8 + t2;
                    float* p1 = p0 + 8 * (size_t)N;
                    *(float2*)p0 = make_float2(acc[mi][ni][0] * out_scale,
                                               acc[mi][ni][1] * out_scale);
                    *(float2*)p1 = make_float2(acc[mi][ni][2] * out_scale,
                                               acc[mi][ni][3] * out_scale);
                    acc[mi][ni][0] = 0.0f; acc[mi][ni][1] = 0.0f;
                    acc[mi][ni][2] = 0.0f; acc[mi][ni][3] = 0.0f;
                }
            }
        }
    }
}

// ---------------------------------------------------------------------------
// Launch
// ---------------------------------------------------------------------------
extern "C" void kernel_launch(void* const* d_in, const int* in_sizes, int n_in,
                              void* d_out, int out_size)
{
    (void)in_sizes; (void)n_in; (void)out_size;
    const float* x   = (const float*)d_in[0];
    const float* U   = (const float*)d_in[1];
    const float* S   = (const float*)d_in[2];
    const float* V   = (const float*)d_in[3];
    const float* dlt = (const float*)d_in[4];
    const float* Q1  = (const float*)d_in[5];
    const float* Q2  = (const float*)d_in[6];
    const float* Q3  = (const float*)d_in[7];
    float* out = (float*)d_out;

    __half *xh, *VTh, *Ush, *Wth;
    float *W0, *W1;
    cudaGetSymbolAddress((void**)&xh,  g_xh);
    cudaGetSymbolAddress((void**)&VTh, g_VTh);
    cudaGetSymbolAddress((void**)&Ush, g_Ush);
    cudaGetSymbolAddress((void**)&Wth, g_Wth);
    cudaGetSymbolAddress((void**)&W0,  g_W0);
    cudaGetSymbolAddress((void**)&W1,  g_W1);

    int nsm = 148;
    cudaDeviceGetAttribute(&nsm, cudaDevAttrMultiProcessorCount, 0);

    cudaFuncSetAttribute(mma_gemm_pers,
                         cudaFuncAttributeMaxDynamicSharedMemorySize, GEMM_SMEM);
    cudaFuncSetAttribute(kron23_kernel,
                         cudaFuncAttributeMaxDynamicSharedMemorySize, 49152);
    cudaFuncSetAttribute(kron1t_kernel,
                         cudaFuncAttributeMaxDynamicSharedMemorySize, K1T_SMEM);

    // 1) x -> xh (fp16, unscaled)
    {
        size_t n4 = (size_t)SEQ_M * IN_F / 4;
        conv_scale_kernel<<<(unsigned)(n4 / 256), 256>>>(
            x, nullptr, nullptr, xh, n4, IN_F, 1.0f);
    }
    // 2) V [k][d] -> VTh [d][k] (x256)
    transpose_conv_kernel<<<dim3(IN_F / 32, IN_F / 32), dim3(32, 8)>>>(
        V, VTh, IN_F, IN_F, 256.0f);
    // 3) U[o][k]*relu(S[k]+delta[k]) -> Ush (x256)
    {
        size_t n4 = (size_t)IN_F * IN_F / 4;
        conv_scale_kernel<<<(unsigned)(n4 / 256), 256>>>(
            U, S, dlt, Ush, n4, IN_F, 256.0f);
    }
    // 4) W^T[d][o] = (VTh @ Ush^T) / 65536   — persistent GEMM
    {
        int ntx = IN_F / 256, ntiles = ntx * (IN_F / 128);
        int grid = nsm < ntiles ? nsm : ntiles;
        mma_gemm_pers<<<grid, NTHR, GEMM_SMEM>>>(
            VTh, Ush, W0, IN_F, IN_F, IN_F, 1.0f / 65536.0f, ntiles, ntx);
    }

    // 5) Kronecker: fused Q3+Q2, then fused Q1+transpose+convert (x256)
    kron23_kernel<<<dim3(IN_F / 64, 16), 256, 49152>>>(W0, W1, Q2, Q3);
    kron1t_kernel<<<dim3(IN_F / 32, 192 / 32), 256, K1T_SMEM>>>(W1, Wth, Q1);

    // 6) out[m][o] = (xh @ Wth^T) / 256   — persistent GEMM
    {
        int ntx = IN_F / 256, ntiles = ntx * (SEQ_M / 128);
        int grid = nsm < ntiles ? nsm : ntiles;
        mma_gemm_pers<<<grid, NTHR, GEMM_SMEM>>>(
            xh, Wth, out, SEQ_M, IN_F, IN_F, 1.0f / 256.0f, ntiles, ntx);
    }
}